// round 5
// baseline (speedup 1.0000x reference)
#include <cuda_runtime.h>
#include <cuda_bf16.h>
#include <math.h>
#include <stdint.h>

#define N_NODES 100000
#define N_EDGES 1600000
#define F_IN    256
#define F_HID   128
#define F_OUT   40
#define NSCAN_BLK 98            // ceil(100000/1024)

// ---------------- device scratch (static globals: allowed) ----------------
__device__ int   g_is64;
__device__ int   g_deg[N_NODES];
__device__ float g_dinv[N_NODES];
__device__ int   g_rowptr[N_NODES + 1];
__device__ int   g_cursor[N_NODES];
__device__ int   g_src[N_EDGES];
__device__ int   g_dst[N_EDGES];
__device__ int   g_ssrc[N_EDGES];       // src ids sorted by dst
__device__ int   g_bsum[NSCAN_BLK];
__device__ float g_H1[(size_t)N_NODES * F_HID];   // x @ W1
__device__ float g_H2[(size_t)N_NODES * F_OUT];   // agg(H1) @ W2 (per-layer2 GEMM)
// W^T baked as N-major bf16 hi/lo: [N][K]
__device__ __align__(16) __nv_bfloat16 g_B1hi[128 * 256];
__device__ __align__(16) __nv_bfloat16 g_B1lo[128 * 256];
__device__ __align__(16) __nv_bfloat16 g_B2hi[64 * 128];
__device__ __align__(16) __nv_bfloat16 g_B2lo[64 * 128];

// ======================= mma.sync helpers ==================================
__device__ __forceinline__ uint32_t smem_u32(const void* p) {
    uint32_t a;
    asm("{ .reg .u64 t; cvta.to.shared.u64 t, %1; cvt.u32.u64 %0, t; }"
        : "=r"(a) : "l"(p));
    return a;
}

__device__ __forceinline__ void ldsm_x4(uint32_t* r, uint32_t addr) {
    asm volatile("ldmatrix.sync.aligned.m8n8.x4.shared.b16 {%0,%1,%2,%3}, [%4];"
                 : "=r"(r[0]), "=r"(r[1]), "=r"(r[2]), "=r"(r[3]) : "r"(addr));
}

__device__ __forceinline__ void mma_bf16(float* c, const uint32_t* a, const uint32_t* b) {
    asm volatile(
        "mma.sync.aligned.m16n8k16.row.col.f32.bf16.bf16.f32 "
        "{%0,%1,%2,%3}, {%4,%5,%6,%7}, {%8,%9}, {%0,%1,%2,%3};"
        : "+f"(c[0]), "+f"(c[1]), "+f"(c[2]), "+f"(c[3])
        : "r"(a[0]), "r"(a[1]), "r"(a[2]), "r"(a[3]), "r"(b[0]), "r"(b[1]));
}

__device__ __forceinline__ uint32_t pack_bf16(float a, float b) {
    __nv_bfloat16 x = __float2bfloat16(a), y = __float2bfloat16(b);
    return ((uint32_t)__bfloat16_as_ushort(y) << 16) | __bfloat16_as_ushort(x);
}

// =================== GEMM1: x @ W1, reg-prefetch pipelined =================
// M x 256 x 128, CTA tile 128x128, 8 warps (4x2), bf16x3 split.
__global__ __launch_bounds__(256, 1) void k_gemm1(
    const float* __restrict__ A, int M,
    const __nv_bfloat16* __restrict__ Bhi,
    const __nv_bfloat16* __restrict__ Blo,
    float* __restrict__ C)
{
    constexpr int KDIM = 256, NDIM = 128, PAD = 72, NJT = 8;
    constexpr int A_HI = 0;
    constexpr int A_LO = 128 * PAD;
    constexpr int B_HI = 2 * 128 * PAD;
    constexpr int B_LO = B_HI + NDIM * PAD;

    extern __shared__ __nv_bfloat16 sm[];
    const uint32_t sb = smem_u32(sm);

    const int tid  = threadIdx.x;
    const int wid  = tid >> 5;
    const int lane = tid & 31;
    const int wm = wid & 3;
    const int wn = wid >> 2;
    const int m_warp = wm * 32;
    const int n_warp = wn * 64;
    const int m0 = blockIdx.x * 128;

    float acc[2][NJT][4];
#pragma unroll
    for (int i = 0; i < 2; i++)
#pragma unroll
        for (int j = 0; j < NJT; j++)
#pragma unroll
            for (int q = 0; q < 4; q++) acc[i][j][q] = 0.f;

    const int a_off = (m_warp + (lane & 15)) * PAD + ((lane >> 4) << 3);
    const int b_off = (n_warp + (lane & 7) + ((lane >> 4) << 3)) * PAD
                    + (((lane >> 3) & 1) << 3);

    float4 areg[8];
    uint4  breg[8];
    // prefetch lambdas (manual)
    #define LOAD_CHUNK(k0) do {                                               \
        _Pragma("unroll")                                                     \
        for (int t = 0; t < 8; t++) {                                         \
            int i = tid + t * 256;                                            \
            int m = i >> 4, q = i & 15;                                       \
            int rowg = m0 + m; if (rowg >= M) rowg = M - 1;                   \
            areg[t] = *(const float4*)(A + (size_t)rowg * KDIM + (k0) + q * 4); \
        }                                                                     \
        _Pragma("unroll")                                                     \
        for (int t = 0; t < 8; t++) {                                         \
            int i = tid + t * 256;                                            \
            int img = i >= NDIM * 8;                                          \
            int ii = i - img * NDIM * 8;                                      \
            int r = ii >> 3, q = ii & 7;                                      \
            const __nv_bfloat16* src = img ? Blo : Bhi;                       \
            breg[t] = *(const uint4*)(src + (size_t)r * KDIM + (k0) + q * 8); \
        }                                                                     \
    } while (0)

    LOAD_CHUNK(0);

    for (int k0 = 0; k0 < KDIM; k0 += 64) {
        // ---- store regs -> smem (A converted to hi/lo) ----
#pragma unroll
        for (int t = 0; t < 8; t++) {
            int i = tid + t * 256;
            int m = i >> 4, q = i & 15;
            float4 v = areg[t];
            uint32_t hp0 = pack_bf16(v.x, v.y);
            uint32_t hp1 = pack_bf16(v.z, v.w);
            __nv_bfloat16 hx = __float2bfloat16(v.x), hy = __float2bfloat16(v.y);
            __nv_bfloat16 hz = __float2bfloat16(v.z), hw = __float2bfloat16(v.w);
            uint32_t lp0 = pack_bf16(v.x - __bfloat162float(hx), v.y - __bfloat162float(hy));
            uint32_t lp1 = pack_bf16(v.z - __bfloat162float(hz), v.w - __bfloat162float(hw));
            *(uint2*)(sm + A_HI + m * PAD + q * 4) = make_uint2(hp0, hp1);
            *(uint2*)(sm + A_LO + m * PAD + q * 4) = make_uint2(lp0, lp1);
        }
#pragma unroll
        for (int t = 0; t < 8; t++) {
            int i = tid + t * 256;
            int img = i >= NDIM * 8;
            int ii = i - img * NDIM * 8;
            int r = ii >> 3, q = ii & 7;
            *(uint4*)(sm + (img ? B_LO : B_HI) + r * PAD + q * 8) = breg[t];
        }
        __syncthreads();

        // ---- prefetch next chunk (LDGs in flight during compute) ----
        if (k0 + 64 < KDIM) LOAD_CHUNK(k0 + 64);

        // ---- compute ----
#pragma unroll
        for (int kk = 0; kk < 64; kk += 16) {
            uint32_t ah[2][4], al[2][4];
#pragma unroll
            for (int i = 0; i < 2; i++) {
                uint32_t base = (uint32_t)((a_off + i * 16 * PAD + kk) * 2);
                ldsm_x4(ah[i], sb + A_HI * 2 + base);
                ldsm_x4(al[i], sb + A_LO * 2 + base);
            }
            uint32_t bh[NJT][2], bl[NJT][2];
#pragma unroll
            for (int jj = 0; jj < NJT / 2; jj++) {
                uint32_t base = (uint32_t)((b_off + jj * 16 * PAD + kk) * 2);
                uint32_t r[4];
                ldsm_x4(r, sb + B_HI * 2 + base);
                bh[2*jj][0] = r[0]; bh[2*jj][1] = r[1];
                bh[2*jj+1][0] = r[2]; bh[2*jj+1][1] = r[3];
                ldsm_x4(r, sb + B_LO * 2 + base);
                bl[2*jj][0] = r[0]; bl[2*jj][1] = r[1];
                bl[2*jj+1][0] = r[2]; bl[2*jj+1][1] = r[3];
            }
#pragma unroll
            for (int i = 0; i < 2; i++)
#pragma unroll
                for (int j = 0; j < NJT; j++) {
                    mma_bf16(acc[i][j], ah[i], bh[j]);
                    mma_bf16(acc[i][j], ah[i], bl[j]);
                    mma_bf16(acc[i][j], al[i], bh[j]);
                }
        }
        __syncthreads();
    }
    #undef LOAD_CHUNK

#pragma unroll
    for (int i = 0; i < 2; i++) {
        int r0 = m0 + m_warp + i * 16 + (lane >> 2);
#pragma unroll
        for (int j = 0; j < NJT; j++) {
            int col = n_warp + j * 8 + (lane & 3) * 2;
            if (r0 < M) {
                C[(size_t)r0 * F_HID + col]     = acc[i][j][0];
                C[(size_t)r0 * F_HID + col + 1] = acc[i][j][1];
            }
            if (r0 + 8 < M) {
                C[(size_t)(r0 + 8) * F_HID + col]     = acc[i][j][2];
                C[(size_t)(r0 + 8) * F_HID + col + 1] = acc[i][j][3];
            }
        }
    }
}

// ============ FUSED: agg1(+bias+relu) -> bf16 split -> GEMM2 ===============
// CTA handles 128 nodes: gathers/aggregates H1 rows into SMEM A tile
// (bf16 hi/lo), then computes H2 = h @ W2 via mma (K=128, N=64, NOUT=40).
__global__ __launch_bounds__(256, 1) void k_agg_gemm2(
    const float* __restrict__ b1,
    const __nv_bfloat16* __restrict__ Bhi,
    const __nv_bfloat16* __restrict__ Blo,
    float* __restrict__ C, int M)
{
    constexpr int KD = 128, ND = 64, PAD = 136, NJT = 4;
    constexpr int A_HI = 0;
    constexpr int A_LO = 128 * PAD;          // 17408
    constexpr int B_HI = 2 * 128 * PAD;      // 34816
    constexpr int B_LO = B_HI + ND * PAD;    // 43520

    extern __shared__ __nv_bfloat16 sm[];
    const uint32_t sb = smem_u32(sm);

    const int tid  = threadIdx.x;
    const int wid  = tid >> 5;
    const int lane = tid & 31;
    const int m0 = blockIdx.x * 128;

    // ---- B fill first (independent of agg) ----
    {
        const int per_img = ND * 16;           // uint4 per image = 1024
#pragma unroll
        for (int t = 0; t < 2 * per_img / 256; t++) {   // 8
            int i = tid + t * 256;
            int img = i >= per_img;
            int ii = i - img * per_img;
            int r = ii >> 4, q = ii & 15;
            const __nv_bfloat16* src = img ? Blo : Bhi;
            uint4 v = *(const uint4*)(src + (size_t)r * KD + q * 8);
            *(uint4*)(sm + (img ? B_LO : B_HI) + r * PAD + q * 8) = v;
        }
    }

    // ---- aggregation phase: warp per node, 16 nodes per warp ----
    float4 bb = ((const float4*)b1)[lane];
    for (int t = 0; t < 16; t++) {
        int node = m0 + wid * 16 + t;
        int nc = node < M ? node : M - 1;
        float di = g_dinv[nc];
        float wself = di * di;

        float4 v = ((const float4*)(g_H1 + (size_t)nc * F_HID))[lane];
        float4 acc;
        acc.x = wself * v.x; acc.y = wself * v.y;
        acc.z = wself * v.z; acc.w = wself * v.w;

        int beg = g_rowptr[nc], end = g_rowptr[nc + 1];
        for (int p0 = beg; p0 < end; p0 += 32) {
            int myp = p0 + lane;
            int s = (myp < end) ? g_ssrc[myp] : 0;
            float ws = (myp < end) ? g_dinv[s] * di : 0.f;
            int cnt = min(32, end - p0);
            int j = 0;
            for (; j + 4 <= cnt; j += 4) {
                int   s0 = __shfl_sync(0xffffffffu, s, j);
                int   s1 = __shfl_sync(0xffffffffu, s, j + 1);
                int   s2 = __shfl_sync(0xffffffffu, s, j + 2);
                int   s3 = __shfl_sync(0xffffffffu, s, j + 3);
                float w0 = __shfl_sync(0xffffffffu, ws, j);
                float w1 = __shfl_sync(0xffffffffu, ws, j + 1);
                float w2 = __shfl_sync(0xffffffffu, ws, j + 2);
                float w3 = __shfl_sync(0xffffffffu, ws, j + 3);
                float4 u0 = ((const float4*)(g_H1 + (size_t)s0 * F_HID))[lane];
                float4 u1 = ((const float4*)(g_H1 + (size_t)s1 * F_HID))[lane];
                float4 u2 = ((const float4*)(g_H1 + (size_t)s2 * F_HID))[lane];
                float4 u3 = ((const float4*)(g_H1 + (size_t)s3 * F_HID))[lane];
                acc.x += w0 * u0.x; acc.y += w0 * u0.y; acc.z += w0 * u0.z; acc.w += w0 * u0.w;
                acc.x += w1 * u1.x; acc.y += w1 * u1.y; acc.z += w1 * u1.z; acc.w += w1 * u1.w;
                acc.x += w2 * u2.x; acc.y += w2 * u2.y; acc.z += w2 * u2.z; acc.w += w2 * u2.w;
                acc.x += w3 * u3.x; acc.y += w3 * u3.y; acc.z += w3 * u3.z; acc.w += w3 * u3.w;
            }
            for (; j < cnt; ++j) {
                int   sj = __shfl_sync(0xffffffffu, s, j);
                float wj = __shfl_sync(0xffffffffu, ws, j);
                float4 u = ((const float4*)(g_H1 + (size_t)sj * F_HID))[lane];
                acc.x += wj * u.x; acc.y += wj * u.y;
                acc.z += wj * u.z; acc.w += wj * u.w;
            }
        }
        acc.x = fmaxf(acc.x + bb.x, 0.f);
        acc.y = fmaxf(acc.y + bb.y, 0.f);
        acc.z = fmaxf(acc.z + bb.z, 0.f);
        acc.w = fmaxf(acc.w + bb.w, 0.f);

        // split and store directly into mma A tile
        __nv_bfloat16 hx = __float2bfloat16(acc.x), hy = __float2bfloat16(acc.y);
        __nv_bfloat16 hz = __float2bfloat16(acc.z), hw = __float2bfloat16(acc.w);
        uint32_t hp0 = ((uint32_t)__bfloat16_as_ushort(hy) << 16) | __bfloat16_as_ushort(hx);
        uint32_t hp1 = ((uint32_t)__bfloat16_as_ushort(hw) << 16) | __bfloat16_as_ushort(hz);
        uint32_t lp0 = pack_bf16(acc.x - __bfloat162float(hx), acc.y - __bfloat162float(hy));
        uint32_t lp1 = pack_bf16(acc.z - __bfloat162float(hz), acc.w - __bfloat162float(hw));
        int r = wid * 16 + t;
        *(uint2*)(sm + A_HI + r * PAD + lane * 4) = make_uint2(hp0, hp1);
        *(uint2*)(sm + A_LO + r * PAD + lane * 4) = make_uint2(lp0, lp1);
    }
    __syncthreads();

    // ---- GEMM2 compute: 128 x 64 x 128, warp layout 4x2 ----
    const int wm = wid & 3;
    const int wn = wid >> 2;
    const int m_warp = wm * 32;
    const int n_warp = wn * 32;

    float acc[2][NJT][4];
#pragma unroll
    for (int i = 0; i < 2; i++)
#pragma unroll
        for (int j = 0; j < NJT; j++)
#pragma unroll
            for (int q = 0; q < 4; q++) acc[i][j][q] = 0.f;

    const int a_off = (m_warp + (lane & 15)) * PAD + ((lane >> 4) << 3);
    const int b_off = (n_warp + (lane & 7) + ((lane >> 4) << 3)) * PAD
                    + (((lane >> 3) & 1) << 3);

#pragma unroll
    for (int kk = 0; kk < KD; kk += 16) {
        uint32_t ah[2][4], al[2][4];
#pragma unroll
        for (int i = 0; i < 2; i++) {
            uint32_t base = (uint32_t)((a_off + i * 16 * PAD + kk) * 2);
            ldsm_x4(ah[i], sb + A_HI * 2 + base);
            ldsm_x4(al[i], sb + A_LO * 2 + base);
        }
        uint32_t bh[NJT][2], bl[NJT][2];
#pragma unroll
        for (int jj = 0; jj < NJT / 2; jj++) {
            uint32_t base = (uint32_t)((b_off + jj * 16 * PAD + kk) * 2);
            uint32_t r[4];
            ldsm_x4(r, sb + B_HI * 2 + base);
            bh[2*jj][0] = r[0]; bh[2*jj][1] = r[1];
            bh[2*jj+1][0] = r[2]; bh[2*jj+1][1] = r[3];
            ldsm_x4(r, sb + B_LO * 2 + base);
            bl[2*jj][0] = r[0]; bl[2*jj][1] = r[1];
            bl[2*jj+1][0] = r[2]; bl[2*jj+1][1] = r[3];
        }
#pragma unroll
        for (int i = 0; i < 2; i++)
#pragma unroll
            for (int j = 0; j < NJT; j++) {
                mma_bf16(acc[i][j], ah[i], bh[j]);
                mma_bf16(acc[i][j], ah[i], bl[j]);
                mma_bf16(acc[i][j], al[i], bh[j]);
            }
    }

    // ---- epilogue: store H2 (40 valid cols) ----
#pragma unroll
    for (int i = 0; i < 2; i++) {
        int r0 = m0 + m_warp + i * 16 + (lane >> 2);
#pragma unroll
        for (int j = 0; j < NJT; j++) {
            int col = n_warp + j * 8 + (lane & 3) * 2;
            if (col < F_OUT) {
                if (r0 < M) {
                    C[(size_t)r0 * F_OUT + col]     = acc[i][j][0];
                    C[(size_t)r0 * F_OUT + col + 1] = acc[i][j][1];
                }
                if (r0 + 8 < M) {
                    C[(size_t)(r0 + 8) * F_OUT + col]     = acc[i][j][2];
                    C[(size_t)(r0 + 8) * F_OUT + col + 1] = acc[i][j][3];
                }
            }
        }
    }
}

// bake W^T (N-major) hi/lo bf16
__global__ void k_prep_b(const float* __restrict__ W, int K, int N, int nact,
                         __nv_bfloat16* __restrict__ hi,
                         __nv_bfloat16* __restrict__ lo) {
    int idx = blockIdx.x * blockDim.x + threadIdx.x;
    if (idx >= N * K) return;
    int n = idx / K, k = idx % K;
    float v = (n < nact) ? W[(size_t)k * nact + n] : 0.f;
    __nv_bfloat16 h = __float2bfloat16(v);
    hi[idx] = h;
    lo[idx] = __float2bfloat16(v - __bfloat162float(h));
}

// ---------------- preproc: dtype detect + deg init (fused) -----------------
__global__ void k_pre0(const unsigned* __restrict__ w) {
    int i = blockIdx.x * blockDim.x + threadIdx.x;
    if (i < N_NODES) g_deg[i] = 1;      // self loop
    if (blockIdx.x == 0) {
        __shared__ int any;
        if (threadIdx.x == 0) any = 0;
        __syncthreads();
        for (int j = threadIdx.x; j < 512; j += blockDim.x)
            if (w[2 * j + 1] != 0u) atomicOr(&any, 1);
        __syncthreads();
        if (threadIdx.x == 0) g_is64 = (any == 0);
    }
}

__global__ void k_convert(const void* __restrict__ ei) {
    int e = blockIdx.x * blockDim.x + threadIdx.x;
    if (e >= N_EDGES) return;
    int s, d;
    if (g_is64) {
        const long long* p = (const long long*)ei;
        s = (int)p[e];
        d = (int)p[N_EDGES + e];
    } else {
        const int* p = (const int*)ei;
        s = p[e];
        d = p[N_EDGES + e];
    }
    g_src[e] = s;
    g_dst[e] = d;
    atomicAdd(&g_deg[d], 1);
}

// ---------------- CSR build: 2-level scan (scan1 also emits dinv) ----------
__global__ void k_scan1() {
    __shared__ int sh[1024];
    int tid = threadIdx.x;
    int i = blockIdx.x * 1024 + tid;
    int v = (i < N_NODES) ? (g_deg[i] - 1) : 0;
    if (i < N_NODES) g_dinv[i] = rsqrtf((float)(v + 1));
    sh[tid] = v;
    __syncthreads();
    for (int off = 1; off < 1024; off <<= 1) {
        int t = (tid >= off) ? sh[tid - off] : 0;
        __syncthreads();
        sh[tid] += t;
        __syncthreads();
    }
    if (i < N_NODES) g_rowptr[i] = sh[tid] - v;   // exclusive
    if (tid == 1023) g_bsum[blockIdx.x] = sh[1023];
}

__global__ void k_scan2() {
    __shared__ int sh[128];
    int tid = threadIdx.x;
    int v = (tid < NSCAN_BLK) ? g_bsum[tid] : 0;
    sh[tid] = v;
    __syncthreads();
    for (int off = 1; off < 128; off <<= 1) {
        int t = (tid >= off) ? sh[tid - off] : 0;
        __syncthreads();
        sh[tid] += t;
        __syncthreads();
    }
    if (tid < NSCAN_BLK) g_bsum[tid] = sh[tid] - v;
}

__global__ void k_scan3() {
    int i = blockIdx.x * blockDim.x + threadIdx.x;
    if (i < N_NODES) {
        int r = g_rowptr[i] + g_bsum[i >> 10];
        g_rowptr[i] = r;
        g_cursor[i] = r;
    } else if (i == N_NODES) {
        g_rowptr[N_NODES] = N_EDGES;
    }
}

__global__ void k_scatter() {
    int e = blockIdx.x * blockDim.x + threadIdx.x;
    if (e >= N_EDGES) return;
    int d = g_dst[e];
    int p = atomicAdd(&g_cursor[d], 1);
    g_ssrc[p] = g_src[e];
}

// ---------- layer-2 aggregation + bias + log_softmax, MLP=4 unrolled ------
__global__ __launch_bounds__(256) void k_agg2(const float* __restrict__ b2,
                                              float* __restrict__ out) {
    int node = (blockIdx.x * blockDim.x + threadIdx.x) >> 5;
    if (node >= N_NODES) return;
    int lane = threadIdx.x & 31;
    float di = g_dinv[node];
    float wself = di * di;

    const float* srow = g_H2 + (size_t)node * F_OUT;
    float acc0 = wself * srow[lane];
    float acc1 = (lane < 8) ? wself * srow[32 + lane] : 0.f;

    int beg = g_rowptr[node], end = g_rowptr[node + 1];
    for (int p0 = beg; p0 < end; p0 += 32) {
        int myp = p0 + lane;
        int s = (myp < end) ? g_ssrc[myp] : 0;
        float ws = (myp < end) ? g_dinv[s] * di : 0.f;
        int cnt = min(32, end - p0);
        int j = 0;
        for (; j + 4 <= cnt; j += 4) {
            int   s0 = __shfl_sync(0xffffffffu, s, j);
            int   s1 = __shfl_sync(0xffffffffu, s, j + 1);
            int   s2 = __shfl_sync(0xffffffffu, s, j + 2);
            int   s3 = __shfl_sync(0xffffffffu, s, j + 3);
            float w0 = __shfl_sync(0xffffffffu, ws, j);
            float w1 = __shfl_sync(0xffffffffu, ws, j + 1);
            float w2 = __shfl_sync(0xffffffffu, ws, j + 2);
            float w3 = __shfl_sync(0xffffffffu, ws, j + 3);
            const float* r0 = g_H2 + (size_t)s0 * F_OUT;
            const float* r1 = g_H2 + (size_t)s1 * F_OUT;
            const float* r2 = g_H2 + (size_t)s2 * F_OUT;
            const float* r3 = g_H2 + (size_t)s3 * F_OUT;
            float a0 = r0[lane], a1 = r1[lane], a2 = r2[lane], a3 = r3[lane];
            acc0 += w0 * a0 + w1 * a1;
            acc0 += w2 * a2 + w3 * a3;
            if (lane < 8) {
                acc1 += w0 * r0[32 + lane] + w1 * r1[32 + lane];
                acc1 += w2 * r2[32 + lane] + w3 * r3[32 + lane];
            }
        }
        for (; j < cnt; ++j) {
            int   sj = __shfl_sync(0xffffffffu, s, j);
            float wj = __shfl_sync(0xffffffffu, ws, j);
            const float* r = g_H2 + (size_t)sj * F_OUT;
            acc0 += wj * r[lane];
            if (lane < 8) acc1 += wj * r[32 + lane];
        }
    }
    acc0 += b2[lane];
    if (lane < 8) acc1 += b2[32 + lane];

    float m = acc0;
    if (lane < 8) m = fmaxf(m, acc1);
#pragma unroll
    for (int o = 16; o; o >>= 1) m = fmaxf(m, __shfl_xor_sync(0xffffffffu, m, o));
    float e = expf(acc0 - m) + ((lane < 8) ? expf(acc1 - m) : 0.f);
#pragma unroll
    for (int o = 16; o; o >>= 1) e += __shfl_xor_sync(0xffffffffu, e, o);
    float lse = m + logf(e);

    float* orow = out + (size_t)node * F_OUT;
    orow[lane] = acc0 - lse;
    if (lane < 8) orow[32 + lane] = acc1 - lse;
}

// ---------------- host launcher --------------------------------------------
extern "C" void kernel_launch(void* const* d_in, const int* in_sizes, int n_in,
                              void* d_out, int out_size) {
    const float* x  = (const float*)d_in[0];
    const void*  ei = d_in[1];
    const float* W1 = (const float*)d_in[2];
    const float* b1 = (const float*)d_in[3];
    const float* W2 = (const float*)d_in[4];
    const float* b2 = (const float*)d_in[5];
    float* out = (float*)d_out;

    float *dH1, *dH2;
    __nv_bfloat16 *dB1hi, *dB1lo, *dB2hi, *dB2lo;
    cudaGetSymbolAddress((void**)&dH1,   g_H1);
    cudaGetSymbolAddress((void**)&dH2,   g_H2);
    cudaGetSymbolAddress((void**)&dB1hi, g_B1hi);
    cudaGetSymbolAddress((void**)&dB1lo, g_B1lo);
    cudaGetSymbolAddress((void**)&dB2hi, g_B2hi);
    cudaGetSymbolAddress((void**)&dB2lo, g_B2lo);

    const int SMEM1 = (2 * 128 + 2 * 128) * 72 * 2;           // 73728
    const int SMEMF = (2 * 128 + 2 * 64) * 136 * 2;           // 104448

    static cudaStream_t s2;
    static cudaEvent_t evFork, evJoin;
    static bool init_done = false;
    if (!init_done) {
        cudaFuncSetAttribute(k_gemm1,
                             cudaFuncAttributeMaxDynamicSharedMemorySize, SMEM1);
        cudaFuncSetAttribute(k_agg_gemm2,
                             cudaFuncAttributeMaxDynamicSharedMemorySize, SMEMF);
        cudaStreamCreateWithFlags(&s2, cudaStreamNonBlocking);
        cudaEventCreateWithFlags(&evFork, cudaEventDisableTiming);
        cudaEventCreateWithFlags(&evJoin, cudaEventDisableTiming);
        init_done = true;
    }

    const int TB = 256;
    int nblkN = (N_NODES + TB - 1) / TB;
    int nblkE = (N_EDGES + TB - 1) / TB;
    int aggBlk = (N_NODES * 32) / TB;
    int gemmBlk = (N_NODES + 127) / 128;          // 782

    // ---- fork: side stream = weights + GEMM1; main stream = CSR build ----
    cudaEventRecord(evFork, 0);
    cudaStreamWaitEvent(s2, evFork, 0);

    k_prep_b<<<(128 * 256 + TB - 1) / TB, TB, 0, s2>>>(W1, 256, 128, 128, dB1hi, dB1lo);
    k_prep_b<<<(64 * 128 + TB - 1) / TB, TB, 0, s2>>>(W2, 128, 64, 40, dB2hi, dB2lo);
    k_gemm1<<<gemmBlk, 256, SMEM1, s2>>>(x, N_NODES, dB1hi, dB1lo, dH1);

    k_pre0<<<nblkN, TB>>>((const unsigned*)ei);
    k_convert<<<nblkE, TB>>>(ei);
    k_scan1<<<NSCAN_BLK, 1024>>>();
    k_scan2<<<1, 128>>>();
    k_scan3<<<(N_NODES + 1 + TB - 1) / TB, TB>>>();
    k_scatter<<<nblkE, TB>>>();

    cudaEventRecord(evJoin, s2);
    cudaStreamWaitEvent(0, evJoin, 0);

    // fused agg1 + GEMM2, then agg2 + log_softmax
    k_agg_gemm2<<<gemmBlk, 256, SMEMF>>>(b1, dB2hi, dB2lo, dH2, N_NODES);
    k_agg2<<<aggBlk, TB>>>(b2, out);
}

// round 6
// speedup vs baseline: 1.1849x; 1.1849x over previous
#include <cuda_runtime.h>
#include <cuda_bf16.h>
#include <math.h>
#include <stdint.h>

#define N_NODES 100000
#define N_EDGES 1600000
#define F_IN    256
#define F_HID   128
#define F_OUT   40
#define NSCAN_BLK 98            // ceil(100000/1024)

// ---------------- device scratch (static globals: allowed) ----------------
__device__ int   g_is64;
__device__ int   g_deg[N_NODES];
__device__ float g_dinv[N_NODES];
__device__ int   g_rowptr[N_NODES + 1];
__device__ int   g_cursor[N_NODES];
__device__ int   g_src[N_EDGES];
__device__ int   g_dst[N_EDGES];
__device__ int   g_ssrc[N_EDGES];       // src ids sorted by dst
__device__ int   g_bsum[NSCAN_BLK];
__device__ uint32_t g_H1b[(size_t)N_NODES * 64];   // x @ W1, packed bf16x2
__device__ float g_h [(size_t)N_NODES * F_HID];    // relu(agg1 + b1), fp32
__device__ float g_H2[(size_t)N_NODES * F_OUT];    // h @ W2
// W^T baked as N-major bf16 hi/lo: [N][K]
__device__ __align__(16) __nv_bfloat16 g_B1hi[128 * 256];
__device__ __align__(16) __nv_bfloat16 g_B1lo[128 * 256];
__device__ __align__(16) __nv_bfloat16 g_B2hi[64 * 128];
__device__ __align__(16) __nv_bfloat16 g_B2lo[64 * 128];

// ======================= mma.sync helpers ==================================
__device__ __forceinline__ uint32_t smem_u32(const void* p) {
    uint32_t a;
    asm("{ .reg .u64 t; cvta.to.shared.u64 t, %1; cvt.u32.u64 %0, t; }"
        : "=r"(a) : "l"(p));
    return a;
}

__device__ __forceinline__ void ldsm_x4(uint32_t* r, uint32_t addr) {
    asm volatile("ldmatrix.sync.aligned.m8n8.x4.shared.b16 {%0,%1,%2,%3}, [%4];"
                 : "=r"(r[0]), "=r"(r[1]), "=r"(r[2]), "=r"(r[3]) : "r"(addr));
}

__device__ __forceinline__ void mma_bf16(float* c, const uint32_t* a, const uint32_t* b) {
    asm volatile(
        "mma.sync.aligned.m16n8k16.row.col.f32.bf16.bf16.f32 "
        "{%0,%1,%2,%3}, {%4,%5,%6,%7}, {%8,%9}, {%0,%1,%2,%3};"
        : "+f"(c[0]), "+f"(c[1]), "+f"(c[2]), "+f"(c[3])
        : "r"(a[0]), "r"(a[1]), "r"(a[2]), "r"(a[3]), "r"(b[0]), "r"(b[1]));
}

__device__ __forceinline__ uint32_t pack_bf16(float a, float b) {
    __nv_bfloat16 x = __float2bfloat16(a), y = __float2bfloat16(b);
    return ((uint32_t)__bfloat16_as_ushort(y) << 16) | __bfloat16_as_ushort(x);
}

// =================== GEMM1: x @ W1, reg-prefetch pipelined =================
// M x 256 x 128, CTA tile 128x128, 8 warps (4x2), bf16x3 split.
// Output: packed bf16x2 H1 (halves layer-1 gather traffic).
__global__ __launch_bounds__(256, 1) void k_gemm1(
    const float* __restrict__ A, int M,
    const __nv_bfloat16* __restrict__ Bhi,
    const __nv_bfloat16* __restrict__ Blo,
    uint32_t* __restrict__ Cb)
{
    constexpr int KDIM = 256, NDIM = 128, PAD = 72, NJT = 8;
    constexpr int A_HI = 0;
    constexpr int A_LO = 128 * PAD;
    constexpr int B_HI = 2 * 128 * PAD;
    constexpr int B_LO = B_HI + NDIM * PAD;

    extern __shared__ __nv_bfloat16 sm[];
    const uint32_t sb = smem_u32(sm);

    const int tid  = threadIdx.x;
    const int wid  = tid >> 5;
    const int lane = tid & 31;
    const int wm = wid & 3;
    const int wn = wid >> 2;
    const int m_warp = wm * 32;
    const int n_warp = wn * 64;
    const int m0 = blockIdx.x * 128;

    float acc[2][NJT][4];
#pragma unroll
    for (int i = 0; i < 2; i++)
#pragma unroll
        for (int j = 0; j < NJT; j++)
#pragma unroll
            for (int q = 0; q < 4; q++) acc[i][j][q] = 0.f;

    const int a_off = (m_warp + (lane & 15)) * PAD + ((lane >> 4) << 3);
    const int b_off = (n_warp + (lane & 7) + ((lane >> 4) << 3)) * PAD
                    + (((lane >> 3) & 1) << 3);

    float4 areg[8];
    uint4  breg[8];
    #define LOAD_CHUNK(k0) do {                                               \
        _Pragma("unroll")                                                     \
        for (int t = 0; t < 8; t++) {                                         \
            int i = tid + t * 256;                                            \
            int m = i >> 4, q = i & 15;                                       \
            int rowg = m0 + m; if (rowg >= M) rowg = M - 1;                   \
            areg[t] = *(const float4*)(A + (size_t)rowg * KDIM + (k0) + q * 4); \
        }                                                                     \
        _Pragma("unroll")                                                     \
        for (int t = 0; t < 8; t++) {                                         \
            int i = tid + t * 256;                                            \
            int img = i >= NDIM * 8;                                          \
            int ii = i - img * NDIM * 8;                                      \
            int r = ii >> 3, q = ii & 7;                                      \
            const __nv_bfloat16* src = img ? Blo : Bhi;                       \
            breg[t] = *(const uint4*)(src + (size_t)r * KDIM + (k0) + q * 8); \
        }                                                                     \
    } while (0)

    LOAD_CHUNK(0);

    for (int k0 = 0; k0 < KDIM; k0 += 64) {
#pragma unroll
        for (int t = 0; t < 8; t++) {
            int i = tid + t * 256;
            int m = i >> 4, q = i & 15;
            float4 v = areg[t];
            __nv_bfloat16 hx = __float2bfloat16(v.x), hy = __float2bfloat16(v.y);
            __nv_bfloat16 hz = __float2bfloat16(v.z), hw = __float2bfloat16(v.w);
            uint32_t hp0 = ((uint32_t)__bfloat16_as_ushort(hy) << 16) | __bfloat16_as_ushort(hx);
            uint32_t hp1 = ((uint32_t)__bfloat16_as_ushort(hw) << 16) | __bfloat16_as_ushort(hz);
            uint32_t lp0 = pack_bf16(v.x - __bfloat162float(hx), v.y - __bfloat162float(hy));
            uint32_t lp1 = pack_bf16(v.z - __bfloat162float(hz), v.w - __bfloat162float(hw));
            *(uint2*)(sm + A_HI + m * PAD + q * 4) = make_uint2(hp0, hp1);
            *(uint2*)(sm + A_LO + m * PAD + q * 4) = make_uint2(lp0, lp1);
        }
#pragma unroll
        for (int t = 0; t < 8; t++) {
            int i = tid + t * 256;
            int img = i >= NDIM * 8;
            int ii = i - img * NDIM * 8;
            int r = ii >> 3, q = ii & 7;
            *(uint4*)(sm + (img ? B_LO : B_HI) + r * PAD + q * 8) = breg[t];
        }
        __syncthreads();

        if (k0 + 64 < KDIM) LOAD_CHUNK(k0 + 64);

#pragma unroll
        for (int kk = 0; kk < 64; kk += 16) {
            uint32_t ah[2][4], al[2][4];
#pragma unroll
            for (int i = 0; i < 2; i++) {
                uint32_t base = (uint32_t)((a_off + i * 16 * PAD + kk) * 2);
                ldsm_x4(ah[i], sb + A_HI * 2 + base);
                ldsm_x4(al[i], sb + A_LO * 2 + base);
            }
            uint32_t bh[NJT][2], bl[NJT][2];
#pragma unroll
            for (int jj = 0; jj < NJT / 2; jj++) {
                uint32_t base = (uint32_t)((b_off + jj * 16 * PAD + kk) * 2);
                uint32_t r[4];
                ldsm_x4(r, sb + B_HI * 2 + base);
                bh[2*jj][0] = r[0]; bh[2*jj][1] = r[1];
                bh[2*jj+1][0] = r[2]; bh[2*jj+1][1] = r[3];
                ldsm_x4(r, sb + B_LO * 2 + base);
                bl[2*jj][0] = r[0]; bl[2*jj][1] = r[1];
                bl[2*jj+1][0] = r[2]; bl[2*jj+1][1] = r[3];
            }
#pragma unroll
            for (int i = 0; i < 2; i++)
#pragma unroll
                for (int j = 0; j < NJT; j++) {
                    mma_bf16(acc[i][j], ah[i], bh[j]);
                    mma_bf16(acc[i][j], ah[i], bl[j]);
                    mma_bf16(acc[i][j], al[i], bh[j]);
                }
        }
        __syncthreads();
    }
    #undef LOAD_CHUNK

    // epilogue: pack adjacent col pair -> one uint32 bf16x2 store
#pragma unroll
    for (int i = 0; i < 2; i++) {
        int r0 = m0 + m_warp + i * 16 + (lane >> 2);
#pragma unroll
        for (int j = 0; j < NJT; j++) {
            int col = n_warp + j * 8 + (lane & 3) * 2;   // even
            if (r0 < M)
                Cb[(size_t)r0 * 64 + (col >> 1)] = pack_bf16(acc[i][j][0], acc[i][j][1]);
            if (r0 + 8 < M)
                Cb[(size_t)(r0 + 8) * 64 + (col >> 1)] = pack_bf16(acc[i][j][2], acc[i][j][3]);
        }
    }
}

// =================== GEMM2: h @ W2 (generic template, fp32 A) =============
template <int KDIM, int NDIM, int LDC, int NOUT>
__global__ __launch_bounds__(256, 1) void k_mma_gemm(
    const float* __restrict__ A, int M,
    const __nv_bfloat16* __restrict__ Bhi,
    const __nv_bfloat16* __restrict__ Blo,
    float* __restrict__ C)
{
    constexpr int PAD = 72;
    constexpr int NJT = (NDIM / 2) / 8;
    constexpr int A_HI = 0;
    constexpr int A_LO = 128 * PAD;
    constexpr int B_HI = 2 * 128 * PAD;
    constexpr int B_LO = B_HI + NDIM * PAD;

    extern __shared__ __nv_bfloat16 sm[];
    const uint32_t sb = smem_u32(sm);

    const int tid  = threadIdx.x;
    const int wid  = tid >> 5;
    const int lane = tid & 31;
    const int wm = wid & 3;
    const int wn = wid >> 2;
    const int m_warp = wm * 32;
    const int n_warp = wn * (NDIM / 2);
    const int m0 = blockIdx.x * 128;

    float acc[2][NJT][4];
#pragma unroll
    for (int i = 0; i < 2; i++)
#pragma unroll
        for (int j = 0; j < NJT; j++)
#pragma unroll
            for (int q = 0; q < 4; q++) acc[i][j][q] = 0.f;

    const int a_off = (m_warp + (lane & 15)) * PAD + ((lane >> 4) << 3);
    const int b_off = (n_warp + (lane & 7) + ((lane >> 4) << 3)) * PAD
                    + (((lane >> 3) & 1) << 3);

    for (int k0 = 0; k0 < KDIM; k0 += 64) {
        __syncthreads();
        {
            const int iters = 128 * 16 / 256;   // 8
#pragma unroll
            for (int t = 0; t < iters; t++) {
                int i = tid + t * 256;
                int m = i >> 4, q = i & 15;
                int rowg = m0 + m; if (rowg >= M) rowg = M - 1;
                float4 v = *(const float4*)(A + (size_t)rowg * KDIM + k0 + q * 4);
                __nv_bfloat16 hx = __float2bfloat16(v.x), hy = __float2bfloat16(v.y);
                __nv_bfloat16 hz = __float2bfloat16(v.z), hw = __float2bfloat16(v.w);
                uint32_t hp0 = ((uint32_t)__bfloat16_as_ushort(hy) << 16) | __bfloat16_as_ushort(hx);
                uint32_t hp1 = ((uint32_t)__bfloat16_as_ushort(hw) << 16) | __bfloat16_as_ushort(hz);
                uint32_t lp0 = pack_bf16(v.x - __bfloat162float(hx), v.y - __bfloat162float(hy));
                uint32_t lp1 = pack_bf16(v.z - __bfloat162float(hz), v.w - __bfloat162float(hw));
                *(uint2*)(sm + A_HI + m * PAD + q * 4) = make_uint2(hp0, hp1);
                *(uint2*)(sm + A_LO + m * PAD + q * 4) = make_uint2(lp0, lp1);
            }
        }
        {
            const int per_img = NDIM * 8;
            const int iters = 2 * per_img / 256;
#pragma unroll
            for (int t = 0; t < iters; t++) {
                int i = tid + t * 256;
                int img = i >= per_img;
                int ii = i - img * per_img;
                int r = ii >> 3, q = ii & 7;
                const __nv_bfloat16* src = img ? Blo : Bhi;
                uint4 v = *(const uint4*)(src + (size_t)r * KDIM + k0 + q * 8);
                *(uint4*)(sm + (img ? B_LO : B_HI) + r * PAD + q * 8) = v;
            }
        }
        __syncthreads();

#pragma unroll
        for (int kk = 0; kk < 64; kk += 16) {
            uint32_t ah[2][4], al[2][4];
#pragma unroll
            for (int i = 0; i < 2; i++) {
                uint32_t base = (uint32_t)((a_off + i * 16 * PAD + kk) * 2);
                ldsm_x4(ah[i], sb + A_HI * 2 + base);
                ldsm_x4(al[i], sb + A_LO * 2 + base);
            }
            uint32_t bh[NJT][2], bl[NJT][2];
#pragma unroll
            for (int jj = 0; jj < NJT / 2; jj++) {
                uint32_t base = (uint32_t)((b_off + jj * 16 * PAD + kk) * 2);
                uint32_t r[4];
                ldsm_x4(r, sb + B_HI * 2 + base);
                bh[2*jj][0] = r[0]; bh[2*jj][1] = r[1];
                bh[2*jj+1][0] = r[2]; bh[2*jj+1][1] = r[3];
                ldsm_x4(r, sb + B_LO * 2 + base);
                bl[2*jj][0] = r[0]; bl[2*jj][1] = r[1];
                bl[2*jj+1][0] = r[2]; bl[2*jj+1][1] = r[3];
            }
#pragma unroll
            for (int i = 0; i < 2; i++)
#pragma unroll
                for (int j = 0; j < NJT; j++) {
                    mma_bf16(acc[i][j], ah[i], bh[j]);
                    mma_bf16(acc[i][j], ah[i], bl[j]);
                    mma_bf16(acc[i][j], al[i], bh[j]);
                }
        }
    }

#pragma unroll
    for (int i = 0; i < 2; i++) {
        int r0 = m0 + m_warp + i * 16 + (lane >> 2);
#pragma unroll
        for (int j = 0; j < NJT; j++) {
            int col = n_warp + j * 8 + (lane & 3) * 2;
            if (col < NOUT) {
                if (r0 < M) {
                    C[(size_t)r0 * LDC + col]     = acc[i][j][0];
                    C[(size_t)r0 * LDC + col + 1] = acc[i][j][1];
                }
                if (r0 + 8 < M) {
                    C[(size_t)(r0 + 8) * LDC + col]     = acc[i][j][2];
                    C[(size_t)(r0 + 8) * LDC + col + 1] = acc[i][j][3];
                }
            }
        }
    }
}

// bake W^T (N-major) hi/lo bf16
__global__ void k_prep_b(const float* __restrict__ W, int K, int N, int nact,
                         __nv_bfloat16* __restrict__ hi,
                         __nv_bfloat16* __restrict__ lo) {
    int idx = blockIdx.x * blockDim.x + threadIdx.x;
    if (idx >= N * K) return;
    int n = idx / K, k = idx % K;
    float v = (n < nact) ? W[(size_t)k * nact + n] : 0.f;
    __nv_bfloat16 h = __float2bfloat16(v);
    hi[idx] = h;
    lo[idx] = __float2bfloat16(v - __bfloat162float(h));
}

// ---------------- preproc: dtype detect + deg init (fused) -----------------
__global__ void k_pre0(const unsigned* __restrict__ w) {
    int i = blockIdx.x * blockDim.x + threadIdx.x;
    if (i < N_NODES) g_deg[i] = 1;      // self loop
    if (blockIdx.x == 0) {
        __shared__ int any;
        if (threadIdx.x == 0) any = 0;
        __syncthreads();
        for (int j = threadIdx.x; j < 512; j += blockDim.x)
            if (w[2 * j + 1] != 0u) atomicOr(&any, 1);
        __syncthreads();
        if (threadIdx.x == 0) g_is64 = (any == 0);
    }
}

__global__ void k_convert(const void* __restrict__ ei) {
    int e = blockIdx.x * blockDim.x + threadIdx.x;
    if (e >= N_EDGES) return;
    int s, d;
    if (g_is64) {
        const long long* p = (const long long*)ei;
        s = (int)p[e];
        d = (int)p[N_EDGES + e];
    } else {
        const int* p = (const int*)ei;
        s = p[e];
        d = p[N_EDGES + e];
    }
    g_src[e] = s;
    g_dst[e] = d;
    atomicAdd(&g_deg[d], 1);
}

// ---------------- CSR build: 2-level scan (scan1 also emits dinv) ----------
__global__ void k_scan1() {
    __shared__ int sh[1024];
    int tid = threadIdx.x;
    int i = blockIdx.x * 1024 + tid;
    int v = (i < N_NODES) ? (g_deg[i] - 1) : 0;
    if (i < N_NODES) g_dinv[i] = rsqrtf((float)(v + 1));
    sh[tid] = v;
    __syncthreads();
    for (int off = 1; off < 1024; off <<= 1) {
        int t = (tid >= off) ? sh[tid - off] : 0;
        __syncthreads();
        sh[tid] += t;
        __syncthreads();
    }
    if (i < N_NODES) g_rowptr[i] = sh[tid] - v;   // exclusive
    if (tid == 1023) g_bsum[blockIdx.x] = sh[1023];
}

__global__ void k_scan2() {
    __shared__ int sh[128];
    int tid = threadIdx.x;
    int v = (tid < NSCAN_BLK) ? g_bsum[tid] : 0;
    sh[tid] = v;
    __syncthreads();
    for (int off = 1; off < 128; off <<= 1) {
        int t = (tid >= off) ? sh[tid - off] : 0;
        __syncthreads();
        sh[tid] += t;
        __syncthreads();
    }
    if (tid < NSCAN_BLK) g_bsum[tid] = sh[tid] - v;
}

__global__ void k_scan3() {
    int i = blockIdx.x * blockDim.x + threadIdx.x;
    if (i < N_NODES) {
        int r = g_rowptr[i] + g_bsum[i >> 10];
        g_rowptr[i] = r;
        g_cursor[i] = r;
    } else if (i == N_NODES) {
        g_rowptr[N_NODES] = N_EDGES;
    }
}

__global__ void k_scatter() {
    int e = blockIdx.x * blockDim.x + threadIdx.x;
    if (e >= N_EDGES) return;
    int d = g_dst[e];
    int p = atomicAdd(&g_cursor[d], 1);
    g_ssrc[p] = g_src[e];
}

// --------- layer-1 aggregation: warp per node, bf16 H1 gather -------------
__device__ __forceinline__ void acc_bf16row(float4& acc, float w, uint2 u) {
    __nv_bfloat162 p0 = *reinterpret_cast<__nv_bfloat162*>(&u.x);
    __nv_bfloat162 p1 = *reinterpret_cast<__nv_bfloat162*>(&u.y);
    acc.x += w * __low2float(p0);
    acc.y += w * __high2float(p0);
    acc.z += w * __low2float(p1);
    acc.w += w * __high2float(p1);
}

__global__ __launch_bounds__(256) void k_agg1(const float* __restrict__ b1) {
    int node = (blockIdx.x * blockDim.x + threadIdx.x) >> 5;
    if (node >= N_NODES) return;
    int lane = threadIdx.x & 31;
    float di = g_dinv[node];
    float wself = di * di;

    float4 acc = make_float4(0.f, 0.f, 0.f, 0.f);
    acc_bf16row(acc, wself, ((const uint2*)(g_H1b + (size_t)node * 64))[lane]);

    int beg = g_rowptr[node], end = g_rowptr[node + 1];
    for (int p0 = beg; p0 < end; p0 += 32) {
        int myp = p0 + lane;
        int s = (myp < end) ? g_ssrc[myp] : 0;
        float ws = (myp < end) ? g_dinv[s] * di : 0.f;
        int cnt = min(32, end - p0);
        int j = 0;
        for (; j + 4 <= cnt; j += 4) {
            int   s0 = __shfl_sync(0xffffffffu, s, j);
            int   s1 = __shfl_sync(0xffffffffu, s, j + 1);
            int   s2 = __shfl_sync(0xffffffffu, s, j + 2);
            int   s3 = __shfl_sync(0xffffffffu, s, j + 3);
            float w0 = __shfl_sync(0xffffffffu, ws, j);
            float w1 = __shfl_sync(0xffffffffu, ws, j + 1);
            float w2 = __shfl_sync(0xffffffffu, ws, j + 2);
            float w3 = __shfl_sync(0xffffffffu, ws, j + 3);
            uint2 u0 = ((const uint2*)(g_H1b + (size_t)s0 * 64))[lane];
            uint2 u1 = ((const uint2*)(g_H1b + (size_t)s1 * 64))[lane];
            uint2 u2 = ((const uint2*)(g_H1b + (size_t)s2 * 64))[lane];
            uint2 u3 = ((const uint2*)(g_H1b + (size_t)s3 * 64))[lane];
            acc_bf16row(acc, w0, u0);
            acc_bf16row(acc, w1, u1);
            acc_bf16row(acc, w2, u2);
            acc_bf16row(acc, w3, u3);
        }
        for (; j < cnt; ++j) {
            int   sj = __shfl_sync(0xffffffffu, s, j);
            float wj = __shfl_sync(0xffffffffu, ws, j);
            acc_bf16row(acc, wj, ((const uint2*)(g_H1b + (size_t)sj * 64))[lane]);
        }
    }
    float4 bb = ((const float4*)b1)[lane];
    acc.x = fmaxf(acc.x + bb.x, 0.f);
    acc.y = fmaxf(acc.y + bb.y, 0.f);
    acc.z = fmaxf(acc.z + bb.z, 0.f);
    acc.w = fmaxf(acc.w + bb.w, 0.f);
    ((float4*)(g_h + (size_t)node * F_HID))[lane] = acc;
}

// ---------- layer-2 aggregation + bias + log_softmax, MLP=4 unrolled ------
__global__ __launch_bounds__(256) void k_agg2(const float* __restrict__ b2,
                                              float* __restrict__ out) {
    int node = (blockIdx.x * blockDim.x + threadIdx.x) >> 5;
    if (node >= N_NODES) return;
    int lane = threadIdx.x & 31;
    float di = g_dinv[node];
    float wself = di * di;

    const float* srow = g_H2 + (size_t)node * F_OUT;
    float acc0 = wself * srow[lane];
    float acc1 = (lane < 8) ? wself * srow[32 + lane] : 0.f;

    int beg = g_rowptr[node], end = g_rowptr[node + 1];
    for (int p0 = beg; p0 < end; p0 += 32) {
        int myp = p0 + lane;
        int s = (myp < end) ? g_ssrc[myp] : 0;
        float ws = (myp < end) ? g_dinv[s] * di : 0.f;
        int cnt = min(32, end - p0);
        int j = 0;
        for (; j + 4 <= cnt; j += 4) {
            int   s0 = __shfl_sync(0xffffffffu, s, j);
            int   s1 = __shfl_sync(0xffffffffu, s, j + 1);
            int   s2 = __shfl_sync(0xffffffffu, s, j + 2);
            int   s3 = __shfl_sync(0xffffffffu, s, j + 3);
            float w0 = __shfl_sync(0xffffffffu, ws, j);
            float w1 = __shfl_sync(0xffffffffu, ws, j + 1);
            float w2 = __shfl_sync(0xffffffffu, ws, j + 2);
            float w3 = __shfl_sync(0xffffffffu, ws, j + 3);
            const float* r0 = g_H2 + (size_t)s0 * F_OUT;
            const float* r1 = g_H2 + (size_t)s1 * F_OUT;
            const float* r2 = g_H2 + (size_t)s2 * F_OUT;
            const float* r3 = g_H2 + (size_t)s3 * F_OUT;
            float a0 = r0[lane], a1 = r1[lane], a2 = r2[lane], a3 = r3[lane];
            acc0 += w0 * a0 + w1 * a1;
            acc0 += w2 * a2 + w3 * a3;
            if (lane < 8) {
                acc1 += w0 * r0[32 + lane] + w1 * r1[32 + lane];
                acc1 += w2 * r2[32 + lane] + w3 * r3[32 + lane];
            }
        }
        for (; j < cnt; ++j) {
            int   sj = __shfl_sync(0xffffffffu, s, j);
            float wj = __shfl_sync(0xffffffffu, ws, j);
            const float* r = g_H2 + (size_t)sj * F_OUT;
            acc0 += wj * r[lane];
            if (lane < 8) acc1 += wj * r[32 + lane];
        }
    }
    acc0 += b2[lane];
    if (lane < 8) acc1 += b2[32 + lane];

    float m = acc0;
    if (lane < 8) m = fmaxf(m, acc1);
#pragma unroll
    for (int o = 16; o; o >>= 1) m = fmaxf(m, __shfl_xor_sync(0xffffffffu, m, o));
    float e = expf(acc0 - m) + ((lane < 8) ? expf(acc1 - m) : 0.f);
#pragma unroll
    for (int o = 16; o; o >>= 1) e += __shfl_xor_sync(0xffffffffu, e, o);
    float lse = m + logf(e);

    float* orow = out + (size_t)node * F_OUT;
    orow[lane] = acc0 - lse;
    if (lane < 8) orow[32 + lane] = acc1 - lse;
}

// ---------------- host launcher --------------------------------------------
extern "C" void kernel_launch(void* const* d_in, const int* in_sizes, int n_in,
                              void* d_out, int out_size) {
    const float* x  = (const float*)d_in[0];
    const void*  ei = d_in[1];
    const float* W1 = (const float*)d_in[2];
    const float* b1 = (const float*)d_in[3];
    const float* W2 = (const float*)d_in[4];
    const float* b2 = (const float*)d_in[5];
    float* out = (float*)d_out;

    float *dh, *dH2;
    uint32_t* dH1b;
    __nv_bfloat16 *dB1hi, *dB1lo, *dB2hi, *dB2lo;
    cudaGetSymbolAddress((void**)&dH1b,  g_H1b);
    cudaGetSymbolAddress((void**)&dh,    g_h);
    cudaGetSymbolAddress((void**)&dH2,   g_H2);
    cudaGetSymbolAddress((void**)&dB1hi, g_B1hi);
    cudaGetSymbolAddress((void**)&dB1lo, g_B1lo);
    cudaGetSymbolAddress((void**)&dB2hi, g_B2hi);
    cudaGetSymbolAddress((void**)&dB2lo, g_B2lo);

    const int SMEM1 = (2 * 128 + 2 * 128) * 72 * 2;   // 73728
    const int SMEM2 = (2 * 128 + 2 * 64) * 72 * 2;    // 55296

    static cudaStream_t s2;
    static cudaEvent_t evFork, evJoin;
    static bool init_done = false;
    if (!init_done) {
        cudaFuncSetAttribute(k_gemm1,
                             cudaFuncAttributeMaxDynamicSharedMemorySize, SMEM1);
        cudaFuncSetAttribute(k_mma_gemm<128, 64, 40, 40>,
                             cudaFuncAttributeMaxDynamicSharedMemorySize, SMEM2);
        cudaStreamCreateWithFlags(&s2, cudaStreamNonBlocking);
        cudaEventCreateWithFlags(&evFork, cudaEventDisableTiming);
        cudaEventCreateWithFlags(&evJoin, cudaEventDisableTiming);
        init_done = true;
    }

    const int TB = 256;
    int nblkN = (N_NODES + TB - 1) / TB;
    int nblkE = (N_EDGES + TB - 1) / TB;
    int aggBlk = (N_NODES * 32) / TB;
    int gemmBlk = (N_NODES + 127) / 128;          // 782

    // ---- fork: side stream = weights + GEMM1; main stream = CSR build ----
    cudaEventRecord(evFork, 0);
    cudaStreamWaitEvent(s2, evFork, 0);

    k_prep_b<<<(128 * 256 + TB - 1) / TB, TB, 0, s2>>>(W1, 256, 128, 128, dB1hi, dB1lo);
    k_prep_b<<<(64 * 128 + TB - 1) / TB, TB, 0, s2>>>(W2, 128, 64, 40, dB2hi, dB2lo);
    k_gemm1<<<gemmBlk, 256, SMEM1, s2>>>(x, N_NODES, dB1hi, dB1lo, dH1b);

    k_pre0<<<nblkN, TB>>>((const unsigned*)ei);
    k_convert<<<nblkE, TB>>>(ei);
    k_scan1<<<NSCAN_BLK, 1024>>>();
    k_scan2<<<1, 128>>>();
    k_scan3<<<(N_NODES + 1 + TB - 1) / TB, TB>>>();
    k_scatter<<<nblkE, TB>>>();

    cudaEventRecord(evJoin, s2);
    cudaStreamWaitEvent(0, evJoin, 0);

    // agg1 (bf16 gather), GEMM2, agg2 + log_softmax
    k_agg1<<<aggBlk, TB>>>(b1);
    k_mma_gemm<128, 64, 40, 40><<<gemmBlk, 256, SMEM2>>>(dh, N_NODES, dB2hi, dB2lo, dH2);
    k_agg2<<<aggBlk, TB>>>(b2, out);
}

// round 8
// speedup vs baseline: 1.2961x; 1.0939x over previous
#include <cuda_runtime.h>
#include <cuda_bf16.h>
#include <math.h>
#include <stdint.h>

#define N_NODES 100000
#define N_EDGES 1600000
#define F_IN    256
#define F_HID   128
#define F_OUT   40
#define NSCAN_BLK 98            // ceil(100000/1024)

// ---------------- device scratch (static globals: allowed) ----------------
__device__ int   g_is64;
__device__ int   g_deg[N_NODES];
__device__ float g_dinv[N_NODES];
__device__ int   g_rowptr[N_NODES + 1];
__device__ int   g_cursor[N_NODES];
__device__ int   g_src[N_EDGES];
__device__ int   g_dst[N_EDGES];
__device__ int   g_ssrc[N_EDGES];       // src ids sorted by dst
__device__ int   g_bsum[NSCAN_BLK];
__device__ uint32_t g_H1b[(size_t)N_NODES * 64];   // x @ W1, packed bf16x2
__device__ uint32_t g_hb [(size_t)N_NODES * 64];   // relu(agg1+b1), packed bf16x2
__device__ uint32_t g_H2b[(size_t)N_NODES * 20];   // h @ W2, packed bf16x2
// W^T baked as N-major bf16 hi/lo: [N][K]
__device__ __align__(16) __nv_bfloat16 g_B1hi[128 * 256];
__device__ __align__(16) __nv_bfloat16 g_B1lo[128 * 256];
__device__ __align__(16) __nv_bfloat16 g_B2hi[64 * 128];
__device__ __align__(16) __nv_bfloat16 g_B2lo[64 * 128];

// ======================= mma.sync helpers ==================================
__device__ __forceinline__ uint32_t smem_u32(const void* p) {
    uint32_t a;
    asm("{ .reg .u64 t; cvta.to.shared.u64 t, %1; cvt.u32.u64 %0, t; }"
        : "=r"(a) : "l"(p));
    return a;
}

__device__ __forceinline__ void ldsm_x4(uint32_t* r, uint32_t addr) {
    asm volatile("ldmatrix.sync.aligned.m8n8.x4.shared.b16 {%0,%1,%2,%3}, [%4];"
                 : "=r"(r[0]), "=r"(r[1]), "=r"(r[2]), "=r"(r[3]) : "r"(addr));
}

__device__ __forceinline__ void mma_bf16(float* c, const uint32_t* a, const uint32_t* b) {
    asm volatile(
        "mma.sync.aligned.m16n8k16.row.col.f32.bf16.bf16.f32 "
        "{%0,%1,%2,%3}, {%4,%5,%6,%7}, {%8,%9}, {%0,%1,%2,%3};"
        : "+f"(c[0]), "+f"(c[1]), "+f"(c[2]), "+f"(c[3])
        : "r"(a[0]), "r"(a[1]), "r"(a[2]), "r"(a[3]), "r"(b[0]), "r"(b[1]));
}

__device__ __forceinline__ uint32_t pack_bf16(float a, float b) {
    __nv_bfloat16 x = __float2bfloat16(a), y = __float2bfloat16(b);
    return ((uint32_t)__bfloat16_as_ushort(y) << 16) | __bfloat16_as_ushort(x);
}

// =================== GEMM1: x @ W1, reg-prefetch pipelined =================
// M x 256 x 128, CTA tile 128x128, 8 warps (4x2), bf16x3 split.
__global__ __launch_bounds__(256, 1) void k_gemm1(
    const float* __restrict__ A, int M,
    const __nv_bfloat16* __restrict__ Bhi,
    const __nv_bfloat16* __restrict__ Blo,
    uint32_t* __restrict__ Cb)
{
    constexpr int KDIM = 256, NDIM = 128, PAD = 72, NJT = 8;
    constexpr int A_HI = 0;
    constexpr int A_LO = 128 * PAD;
    constexpr int B_HI = 2 * 128 * PAD;
    constexpr int B_LO = B_HI + NDIM * PAD;

    extern __shared__ __nv_bfloat16 sm[];
    const uint32_t sb = smem_u32(sm);

    const int tid  = threadIdx.x;
    const int wid  = tid >> 5;
    const int lane = tid & 31;
    const int wm = wid & 3;
    const int wn = wid >> 2;
    const int m_warp = wm * 32;
    const int n_warp = wn * 64;
    const int m0 = blockIdx.x * 128;

    float acc[2][NJT][4];
#pragma unroll
    for (int i = 0; i < 2; i++)
#pragma unroll
        for (int j = 0; j < NJT; j++)
#pragma unroll
            for (int q = 0; q < 4; q++) acc[i][j][q] = 0.f;

    const int a_off = (m_warp + (lane & 15)) * PAD + ((lane >> 4) << 3);
    const int b_off = (n_warp + (lane & 7) + ((lane >> 4) << 3)) * PAD
                    + (((lane >> 3) & 1) << 3);

    float4 areg[8];
    uint4  breg[8];
    #define LOAD_CHUNK(k0) do {                                               \
        _Pragma("unroll")                                                     \
        for (int t = 0; t < 8; t++) {                                         \
            int i = tid + t * 256;                                            \
            int m = i >> 4, q = i & 15;                                       \
            int rowg = m0 + m; if (rowg >= M) rowg = M - 1;                   \
            areg[t] = *(const float4*)(A + (size_t)rowg * KDIM + (k0) + q * 4); \
        }                                                                     \
        _Pragma("unroll")                                                     \
        for (int t = 0; t < 8; t++) {                                         \
            int i = tid + t * 256;                                            \
            int img = i >= NDIM * 8;                                          \
            int ii = i - img * NDIM * 8;                                      \
            int r = ii >> 3, q = ii & 7;                                      \
            const __nv_bfloat16* src = img ? Blo : Bhi;                       \
            breg[t] = *(const uint4*)(src + (size_t)r * KDIM + (k0) + q * 8); \
        }                                                                     \
    } while (0)

    LOAD_CHUNK(0);

    for (int k0 = 0; k0 < KDIM; k0 += 64) {
#pragma unroll
        for (int t = 0; t < 8; t++) {
            int i = tid + t * 256;
            int m = i >> 4, q = i & 15;
            float4 v = areg[t];
            __nv_bfloat16 hx = __float2bfloat16(v.x), hy = __float2bfloat16(v.y);
            __nv_bfloat16 hz = __float2bfloat16(v.z), hw = __float2bfloat16(v.w);
            uint32_t hp0 = ((uint32_t)__bfloat16_as_ushort(hy) << 16) | __bfloat16_as_ushort(hx);
            uint32_t hp1 = ((uint32_t)__bfloat16_as_ushort(hw) << 16) | __bfloat16_as_ushort(hz);
            uint32_t lp0 = pack_bf16(v.x - __bfloat162float(hx), v.y - __bfloat162float(hy));
            uint32_t lp1 = pack_bf16(v.z - __bfloat162float(hz), v.w - __bfloat162float(hw));
            *(uint2*)(sm + A_HI + m * PAD + q * 4) = make_uint2(hp0, hp1);
            *(uint2*)(sm + A_LO + m * PAD + q * 4) = make_uint2(lp0, lp1);
        }
#pragma unroll
        for (int t = 0; t < 8; t++) {
            int i = tid + t * 256;
            int img = i >= NDIM * 8;
            int ii = i - img * NDIM * 8;
            int r = ii >> 3, q = ii & 7;
            *(uint4*)(sm + (img ? B_LO : B_HI) + r * PAD + q * 8) = breg[t];
        }
        __syncthreads();

        if (k0 + 64 < KDIM) LOAD_CHUNK(k0 + 64);

#pragma unroll
        for (int kk = 0; kk < 64; kk += 16) {
            uint32_t ah[2][4], al[2][4];
#pragma unroll
            for (int i = 0; i < 2; i++) {
                uint32_t base = (uint32_t)((a_off + i * 16 * PAD + kk) * 2);
                ldsm_x4(ah[i], sb + A_HI * 2 + base);
                ldsm_x4(al[i], sb + A_LO * 2 + base);
            }
            uint32_t bh[NJT][2], bl[NJT][2];
#pragma unroll
            for (int jj = 0; jj < NJT / 2; jj++) {
                uint32_t base = (uint32_t)((b_off + jj * 16 * PAD + kk) * 2);
                uint32_t r[4];
                ldsm_x4(r, sb + B_HI * 2 + base);
                bh[2*jj][0] = r[0]; bh[2*jj][1] = r[1];
                bh[2*jj+1][0] = r[2]; bh[2*jj+1][1] = r[3];
                ldsm_x4(r, sb + B_LO * 2 + base);
                bl[2*jj][0] = r[0]; bl[2*jj][1] = r[1];
                bl[2*jj+1][0] = r[2]; bl[2*jj+1][1] = r[3];
            }
#pragma unroll
            for (int i = 0; i < 2; i++)
#pragma unroll
                for (int j = 0; j < NJT; j++) {
                    mma_bf16(acc[i][j], ah[i], bh[j]);
                    mma_bf16(acc[i][j], ah[i], bl[j]);
                    mma_bf16(acc[i][j], al[i], bh[j]);
                }
        }
        __syncthreads();
    }
    #undef LOAD_CHUNK

#pragma unroll
    for (int i = 0; i < 2; i++) {
        int r0 = m0 + m_warp + i * 16 + (lane >> 2);
#pragma unroll
        for (int j = 0; j < NJT; j++) {
            int col = n_warp + j * 8 + (lane & 3) * 2;
            if (r0 < M)
                Cb[(size_t)r0 * 64 + (col >> 1)] = pack_bf16(acc[i][j][0], acc[i][j][1]);
            if (r0 + 8 < M)
                Cb[(size_t)(r0 + 8) * 64 + (col >> 1)] = pack_bf16(acc[i][j][2], acc[i][j][3]);
        }
    }
}

// =================== GEMM2: hb(bf16) @ W2, 2-pass mma ======================
// A already exact bf16 -> only B split. K=128 (single chunk), N=64.
// Rows in SMEM are full-K: PAD2 = 136 bf16 (128 data + 8 pad).
__global__ __launch_bounds__(256, 1) void k_gemm2(
    const uint32_t* __restrict__ Ab, int M,
    const __nv_bfloat16* __restrict__ Bhi,
    const __nv_bfloat16* __restrict__ Blo,
    uint32_t* __restrict__ Cb)
{
    constexpr int KDIM = 128, NDIM = 64, PAD2 = 136, NJT = 4;
    constexpr int A_HI = 0;                    // 128 rows x 136
    constexpr int B_HI = 128 * PAD2;           // 17408
    constexpr int B_LO = B_HI + NDIM * PAD2;   // 26112
    // total bf16: 26112 + 64*136 = 34816 -> 69632 bytes

    extern __shared__ __nv_bfloat16 sm[];
    const uint32_t sb = smem_u32(sm);

    const int tid  = threadIdx.x;
    const int wid  = tid >> 5;
    const int lane = tid & 31;
    const int wm = wid & 3;
    const int wn = wid >> 2;
    const int m_warp = wm * 32;
    const int n_warp = wn * 32;
    const int m0 = blockIdx.x * 128;

    // ---- A fill: 128 rows x 16 uint4 (= 128 bf16) -> 2048 uint4, 8 iters ----
#pragma unroll
    for (int t = 0; t < 8; t++) {
        int i = tid + t * 256;
        int r = i >> 4, q = i & 15;
        int rowg = m0 + r; if (rowg >= M) rowg = M - 1;
        uint4 v = *(const uint4*)(Ab + (size_t)rowg * 64 + q * 4);
        *(uint4*)(sm + A_HI + r * PAD2 + q * 8) = v;
    }
    // ---- B fill: 2 images x 64 rows x 16 uint4 = 2048 uint4, 8 iters ----
#pragma unroll
    for (int t = 0; t < 8; t++) {
        int i = tid + t * 256;
        int img = i >= 1024;
        int ii = i - img * 1024;
        int r = ii >> 4, q = ii & 15;
        const __nv_bfloat16* src = img ? Blo : Bhi;
        uint4 v = *(const uint4*)(src + (size_t)r * KDIM + q * 8);
        *(uint4*)(sm + (img ? B_LO : B_HI) + r * PAD2 + q * 8) = v;
    }
    __syncthreads();

    float acc[2][NJT][4];
#pragma unroll
    for (int i = 0; i < 2; i++)
#pragma unroll
        for (int j = 0; j < NJT; j++)
#pragma unroll
            for (int q = 0; q < 4; q++) acc[i][j][q] = 0.f;

    const int a_off = (m_warp + (lane & 15)) * PAD2 + ((lane >> 4) << 3);
    const int b_off = (n_warp + (lane & 7) + ((lane >> 4) << 3)) * PAD2
                    + (((lane >> 3) & 1) << 3);

#pragma unroll
    for (int kk = 0; kk < KDIM; kk += 16) {
        uint32_t ah[2][4];
#pragma unroll
        for (int i = 0; i < 2; i++) {
            uint32_t base = (uint32_t)((a_off + i * 16 * PAD2 + kk) * 2);
            ldsm_x4(ah[i], sb + A_HI * 2 + base);
        }
        uint32_t bh[NJT][2], bl[NJT][2];
#pragma unroll
        for (int jj = 0; jj < NJT / 2; jj++) {
            uint32_t base = (uint32_t)((b_off + jj * 16 * PAD2 + kk) * 2);
            uint32_t r[4];
            ldsm_x4(r, sb + B_HI * 2 + base);
            bh[2*jj][0] = r[0]; bh[2*jj][1] = r[1];
            bh[2*jj+1][0] = r[2]; bh[2*jj+1][1] = r[3];
            ldsm_x4(r, sb + B_LO * 2 + base);
            bl[2*jj][0] = r[0]; bl[2*jj][1] = r[1];
            bl[2*jj+1][0] = r[2]; bl[2*jj+1][1] = r[3];
        }
#pragma unroll
        for (int i = 0; i < 2; i++)
#pragma unroll
            for (int j = 0; j < NJT; j++) {
                mma_bf16(acc[i][j], ah[i], bh[j]);
                mma_bf16(acc[i][j], ah[i], bl[j]);
            }
    }

    // epilogue: pack col pairs -> H2b (20 u32 per row, cols < 40)
#pragma unroll
    for (int i = 0; i < 2; i++) {
        int r0 = m0 + m_warp + i * 16 + (lane >> 2);
#pragma unroll
        for (int j = 0; j < NJT; j++) {
            int col = n_warp + j * 8 + (lane & 3) * 2;
            if (col < F_OUT) {
                if (r0 < M)
                    Cb[(size_t)r0 * 20 + (col >> 1)] = pack_bf16(acc[i][j][0], acc[i][j][1]);
                if (r0 + 8 < M)
                    Cb[(size_t)(r0 + 8) * 20 + (col >> 1)] = pack_bf16(acc[i][j][2], acc[i][j][3]);
            }
        }
    }
}

// bake W^T (N-major) hi/lo bf16
__global__ void k_prep_b(const float* __restrict__ W, int K, int N, int nact,
                         __nv_bfloat16* __restrict__ hi,
                         __nv_bfloat16* __restrict__ lo) {
    int idx = blockIdx.x * blockDim.x + threadIdx.x;
    if (idx >= N * K) return;
    int n = idx / K, k = idx % K;
    float v = (n < nact) ? W[(size_t)k * nact + n] : 0.f;
    __nv_bfloat16 h = __float2bfloat16(v);
    hi[idx] = h;
    lo[idx] = __float2bfloat16(v - __bfloat162float(h));
}

// ---------------- preproc: dtype detect + deg init (fused) -----------------
__global__ void k_pre0(const unsigned* __restrict__ w) {
    int i = blockIdx.x * blockDim.x + threadIdx.x;
    if (i < N_NODES) g_deg[i] = 1;      // self loop
    if (blockIdx.x == 0) {
        __shared__ int any;
        if (threadIdx.x == 0) any = 0;
        __syncthreads();
        for (int j = threadIdx.x; j < 512; j += blockDim.x)
            if (w[2 * j + 1] != 0u) atomicOr(&any, 1);
        __syncthreads();
        if (threadIdx.x == 0) g_is64 = (any == 0);
    }
}

__global__ void k_convert(const void* __restrict__ ei) {
    int e = blockIdx.x * blockDim.x + threadIdx.x;
    if (e >= N_EDGES) return;
    int s, d;
    if (g_is64) {
        const long long* p = (const long long*)ei;
        s = (int)p[e];
        d = (int)p[N_EDGES + e];
    } else {
        const int* p = (const int*)ei;
        s = p[e];
        d = p[N_EDGES + e];
    }
    g_src[e] = s;
    g_dst[e] = d;
    atomicAdd(&g_deg[d], 1);
}

// ---------------- CSR build: 2-level scan (scan1 also emits dinv) ----------
__global__ void k_scan1() {
    __shared__ int sh[1024];
    int tid = threadIdx.x;
    int i = blockIdx.x * 1024 + tid;
    int v = (i < N_NODES) ? (g_deg[i] - 1) : 0;
    if (i < N_NODES) g_dinv[i] = rsqrtf((float)(v + 1));
    sh[tid] = v;
    __syncthreads();
    for (int off = 1; off < 1024; off <<= 1) {
        int t = (tid >= off) ? sh[tid - off] : 0;
        __syncthreads();
        sh[tid] += t;
        __syncthreads();
    }
    if (i < N_NODES) g_rowptr[i] = sh[tid] - v;   // exclusive
    if (tid == 1023) g_bsum[blockIdx.x] = sh[1023];
}

__global__ void k_scan2() {
    __shared__ int sh[128];
    int tid = threadIdx.x;
    int v = (tid < NSCAN_BLK) ? g_bsum[tid] : 0;
    sh[tid] = v;
    __syncthreads();
    for (int off = 1; off < 128; off <<= 1) {
        int t = (tid >= off) ? sh[tid - off] : 0;
        __syncthreads();
        sh[tid] += t;
        __syncthreads();
    }
    if (tid < NSCAN_BLK) g_bsum[tid] = sh[tid] - v;
}

__global__ void k_scan3() {
    int i = blockIdx.x * blockDim.x + threadIdx.x;
    if (i < N_NODES) {
        int r = g_rowptr[i] + g_bsum[i >> 10];
        g_rowptr[i] = r;
        g_cursor[i] = r;
    } else if (i == N_NODES) {
        g_rowptr[N_NODES] = N_EDGES;
    }
}

__global__ void k_scatter() {
    int e = blockIdx.x * blockDim.x + threadIdx.x;
    if (e >= N_EDGES) return;
    int d = g_dst[e];
    int p = atomicAdd(&g_cursor[d], 1);
    g_ssrc[p] = g_src[e];
}

// --------- layer-1 aggregation: warp per node, bf16 in / bf16 out ---------
__device__ __forceinline__ void acc_bf16row(float4& acc, float w, uint2 u) {
    __nv_bfloat162 p0 = *reinterpret_cast<__nv_bfloat162*>(&u.x);
    __nv_bfloat162 p1 = *reinterpret_cast<__nv_bfloat162*>(&u.y);
    acc.x += w * __low2float(p0);
    acc.y += w * __high2float(p0);
    acc.z += w * __low2float(p1);
    acc.w += w * __high2float(p1);
}

__global__ __launch_bounds__(256) void k_agg1(const float* __restrict__ b1) {
    int node = (blockIdx.x * blockDim.x + threadIdx.x) >> 5;
    if (node >= N_NODES) return;
    int lane = threadIdx.x & 31;
    float di = g_dinv[node];
    float wself = di * di;

    float4 acc = make_float4(0.f, 0.f, 0.f, 0.f);
    acc_bf16row(acc, wself, ((const uint2*)(g_H1b + (size_t)node * 64))[lane]);

    int beg = g_rowptr[node], end = g_rowptr[node + 1];
    for (int p0 = beg; p0 < end; p0 += 32) {
        int myp = p0 + lane;
        int s = (myp < end) ? g_ssrc[myp] : 0;
        float ws = (myp < end) ? g_dinv[s] * di : 0.f;
        int cnt = min(32, end - p0);
        int j = 0;
        for (; j + 4 <= cnt; j += 4) {
            int   s0 = __shfl_sync(0xffffffffu, s, j);
            int   s1 = __shfl_sync(0xffffffffu, s, j + 1);
            int   s2 = __shfl_sync(0xffffffffu, s, j + 2);
            int   s3 = __shfl_sync(0xffffffffu, s, j + 3);
            float w0 = __shfl_sync(0xffffffffu, ws, j);
            float w1 = __shfl_sync(0xffffffffu, ws, j + 1);
            float w2 = __shfl_sync(0xffffffffu, ws, j + 2);
            float w3 = __shfl_sync(0xffffffffu, ws, j + 3);
            uint2 u0 = ((const uint2*)(g_H1b + (size_t)s0 * 64))[lane];
            uint2 u1 = ((const uint2*)(g_H1b + (size_t)s1 * 64))[lane];
            uint2 u2 = ((const uint2*)(g_H1b + (size_t)s2 * 64))[lane];
            uint2 u3 = ((const uint2*)(g_H1b + (size_t)s3 * 64))[lane];
            acc_bf16row(acc, w0, u0);
            acc_bf16row(acc, w1, u1);
            acc_bf16row(acc, w2, u2);
            acc_bf16row(acc, w3, u3);
        }
        for (; j < cnt; ++j) {
            int   sj = __shfl_sync(0xffffffffu, s, j);
            float wj = __shfl_sync(0xffffffffu, ws, j);
            acc_bf16row(acc, wj, ((const uint2*)(g_H1b + (size_t)sj * 64))[lane]);
        }
    }
    float4 bb = ((const float4*)b1)[lane];
    acc.x = fmaxf(acc.x + bb.x, 0.f);
    acc.y = fmaxf(acc.y + bb.y, 0.f);
    acc.z = fmaxf(acc.z + bb.z, 0.f);
    acc.w = fmaxf(acc.w + bb.w, 0.f);
    uint2 packed = make_uint2(pack_bf16(acc.x, acc.y), pack_bf16(acc.z, acc.w));
    ((uint2*)(g_hb + (size_t)node * 64))[lane] = packed;
}

// ---- layer-2 aggregation (bf16 H2 gather) + bias + log_softmax ------------
__global__ __launch_bounds__(256) void k_agg2(const float* __restrict__ b2,
                                              float* __restrict__ out) {
    int node = (blockIdx.x * blockDim.x + threadIdx.x) >> 5;
    if (node >= N_NODES) return;
    int lane = threadIdx.x & 31;
    bool act = lane < 20;                  // 20 u32 = 40 cols
    float di = g_dinv[node];
    float wself = di * di;

    int llane = act ? lane : 0;            // clamp for safe addressing
    float acc0 = 0.f, acc1 = 0.f;          // cols 2*lane, 2*lane+1
    {
        uint32_t u = g_H2b[(size_t)node * 20 + llane];
        __nv_bfloat162 p = *reinterpret_cast<__nv_bfloat162*>(&u);
        acc0 = wself * __low2float(p);
        acc1 = wself * __high2float(p);
    }

    int beg = g_rowptr[node], end = g_rowptr[node + 1];
    for (int p0 = beg; p0 < end; p0 += 32) {
        int myp = p0 + lane;
        int s = (myp < end) ? g_ssrc[myp] : 0;
        float ws = (myp < end) ? g_dinv[s] * di : 0.f;
        int cnt = min(32, end - p0);
        int j = 0;
        for (; j + 4 <= cnt; j += 4) {
            int   s0 = __shfl_sync(0xffffffffu, s, j);
            int   s1 = __shfl_sync(0xffffffffu, s, j + 1);
            int   s2 = __shfl_sync(0xffffffffu, s, j + 2);
            int   s3 = __shfl_sync(0xffffffffu, s, j + 3);
            float w0 = __shfl_sync(0xffffffffu, ws, j);
            float w1 = __shfl_sync(0xffffffffu, ws, j + 1);
            float w2 = __shfl_sync(0xffffffffu, ws, j + 2);
            float w3 = __shfl_sync(0xffffffffu, ws, j + 3);
            uint32_t u0 = g_H2b[(size_t)s0 * 20 + llane];
            uint32_t u1 = g_H2b[(size_t)s1 * 20 + llane];
            uint32_t u2 = g_H2b[(size_t)s2 * 20 + llane];
            uint32_t u3 = g_H2b[(size_t)s3 * 20 + llane];
            __nv_bfloat162 q0 = *reinterpret_cast<__nv_bfloat162*>(&u0);
            __nv_bfloat162 q1 = *reinterpret_cast<__nv_bfloat162*>(&u1);
            __nv_bfloat162 q2 = *reinterpret_cast<__nv_bfloat162*>(&u2);
            __nv_bfloat162 q3 = *reinterpret_cast<__nv_bfloat162*>(&u3);
            acc0 += w0 * __low2float(q0) + w1 * __low2float(q1)
                  + w2 * __low2float(q2) + w3 * __low2float(q3);
            acc1 += w0 * __high2float(q0) + w1 * __high2float(q1)
                  + w2 * __high2float(q2) + w3 * __high2float(q3);
        }
        for (; j < cnt; ++j) {
            int   sj = __shfl_sync(0xffffffffu, s, j);
            float wj = __shfl_sync(0xffffffffu, ws, j);
            uint32_t u = g_H2b[(size_t)sj * 20 + llane];
            __nv_bfloat162 q = *reinterpret_cast<__nv_bfloat162*>(&u);
            acc0 += wj * __low2float(q);
            acc1 += wj * __high2float(q);
        }
    }
    acc0 += b2[2 * llane];
    acc1 += b2[2 * llane + 1];

    // warp log_softmax over 40 values (2 per active lane)
    float m = act ? fmaxf(acc0, acc1) : -1e30f;
#pragma unroll
    for (int o = 16; o; o >>= 1) m = fmaxf(m, __shfl_xor_sync(0xffffffffu, m, o));
    float e = act ? (expf(acc0 - m) + expf(acc1 - m)) : 0.f;
#pragma unroll
    for (int o = 16; o; o >>= 1) e += __shfl_xor_sync(0xffffffffu, e, o);
    float lse = m + logf(e);

    if (act) {
        float2 o2 = make_float2(acc0 - lse, acc1 - lse);
        *(float2*)(out + (size_t)node * F_OUT + 2 * lane) = o2;
    }
}

// ---------------- host launcher --------------------------------------------
extern "C" void kernel_launch(void* const* d_in, const int* in_sizes, int n_in,
                              void* d_out, int out_size) {
    const float* x  = (const float*)d_in[0];
    const void*  ei = d_in[1];
    const float* W1 = (const float*)d_in[2];
    const float* b1 = (const float*)d_in[3];
    const float* W2 = (const float*)d_in[4];
    const float* b2 = (const float*)d_in[5];
    float* out = (float*)d_out;

    uint32_t *dH1b, *dhb, *dH2b;
    __nv_bfloat16 *dB1hi, *dB1lo, *dB2hi, *dB2lo;
    cudaGetSymbolAddress((void**)&dH1b,  g_H1b);
    cudaGetSymbolAddress((void**)&dhb,   g_hb);
    cudaGetSymbolAddress((void**)&dH2b,  g_H2b);
    cudaGetSymbolAddress((void**)&dB1hi, g_B1hi);
    cudaGetSymbolAddress((void**)&dB1lo, g_B1lo);
    cudaGetSymbolAddress((void**)&dB2hi, g_B2hi);
    cudaGetSymbolAddress((void**)&dB2lo, g_B2lo);

    const int SMEM1 = (2 * 128 + 2 * 128) * 72 * 2;   // 73728
    const int SMEM2 = (128 + 2 * 64) * 136 * 2;       // 69632

    static cudaStream_t s2;
    static cudaEvent_t evFork, evJoin;
    static bool init_done = false;
    if (!init_done) {
        cudaFuncSetAttribute(k_gemm1,
                             cudaFuncAttributeMaxDynamicSharedMemorySize, SMEM1);
        cudaFuncSetAttribute(k_gemm2,
                             cudaFuncAttributeMaxDynamicSharedMemorySize, SMEM2);
        cudaStreamCreateWithFlags(&s2, cudaStreamNonBlocking);
        cudaEventCreateWithFlags(&evFork, cudaEventDisableTiming);
        cudaEventCreateWithFlags(&evJoin, cudaEventDisableTiming);
        init_done = true;
    }

    const int TB = 256;
    int nblkN = (N_NODES + TB - 1) / TB;
    int nblkE = (N_EDGES + TB - 1) / TB;
    int aggBlk = (N_NODES * 32) / TB;
    int gemmBlk = (N_NODES + 127) / 128;          // 782

    // ---- fork: side stream = weights + GEMM1; main stream = CSR build ----
    cudaEventRecord(evFork, 0);
    cudaStreamWaitEvent(s2, evFork, 0);

    k_prep_b<<<(128 * 256 + TB - 1) / TB, TB, 0, s2>>>(W1, 256, 128, 128, dB1hi, dB1lo);
    k_prep_b<<<(64 * 128 + TB - 1) / TB, TB, 0, s2>>>(W2, 128, 64, 40, dB2hi, dB2lo);
    k_gemm1<<<gemmBlk, 256, SMEM1, s2>>>(x, N_NODES, dB1hi, dB1lo, dH1b);

    k_pre0<<<nblkN, TB>>>((const unsigned*)ei);
    k_convert<<<nblkE, TB>>>(ei);
    k_scan1<<<NSCAN_BLK, 1024>>>();
    k_scan2<<<1, 128>>>();
    k_scan3<<<(N_NODES + 1 + TB - 1) / TB, TB>>>();
    k_scatter<<<nblkE, TB>>>();

    cudaEventRecord(evJoin, s2);
    cudaStreamWaitEvent(0, evJoin, 0);

    // agg1 (bf16 in/out), GEMM2 (2-pass), agg2 (bf16 gather) + log_softmax
    k_agg1<<<aggBlk, TB>>>(b1);
    k_gemm2<<<gemmBlk, 256, SMEM2>>>(dhb, N_NODES, dB2hi, dB2lo, dH2b);
    k_agg2<<<aggBlk, TB>>>(b2, out);
}

// round 9
// speedup vs baseline: 1.4088x; 1.0869x over previous
#include <cuda_runtime.h>
#include <cuda_bf16.h>
#include <math.h>
#include <stdint.h>

#define N_NODES 100000
#define N_EDGES 1600000
#define F_IN    256
#define F_HID   128
#define F_OUT   40
#define NSCAN_BLK 98            // ceil(100000/1024)

// ---------------- device scratch (static globals: allowed) ----------------
__device__ int   g_is64;
__device__ int   g_deg[N_NODES];
__device__ float g_dinv[N_NODES];
__device__ int   g_rowptr[N_NODES + 1];
__device__ int   g_cursor[N_NODES];
__device__ int   g_src[N_EDGES];
__device__ int   g_dst[N_EDGES];
__device__ int   g_ssrc[N_EDGES];       // src ids sorted by dst
__device__ int   g_bsum[NSCAN_BLK];
__device__ uint32_t g_H1b[(size_t)N_NODES * 64];   // x @ W1, packed bf16x2
__device__ uint32_t g_hb [(size_t)N_NODES * 64];   // relu(agg1+b1), packed bf16x2
__device__ uint32_t g_H2b[(size_t)N_NODES * 20];   // h @ W2, packed bf16x2
// W^T baked as N-major bf16 (hi only): [N][K]
__device__ __align__(16) __nv_bfloat16 g_B1hi[128 * 256];
__device__ __align__(16) __nv_bfloat16 g_B2hi[64 * 128];

// ======================= mma.sync helpers ==================================
__device__ __forceinline__ uint32_t smem_u32(const void* p) {
    uint32_t a;
    asm("{ .reg .u64 t; cvta.to.shared.u64 t, %1; cvt.u32.u64 %0, t; }"
        : "=r"(a) : "l"(p));
    return a;
}

__device__ __forceinline__ void ldsm_x4(uint32_t* r, uint32_t addr) {
    asm volatile("ldmatrix.sync.aligned.m8n8.x4.shared.b16 {%0,%1,%2,%3}, [%4];"
                 : "=r"(r[0]), "=r"(r[1]), "=r"(r[2]), "=r"(r[3]) : "r"(addr));
}

__device__ __forceinline__ void mma_bf16(float* c, const uint32_t* a, const uint32_t* b) {
    asm volatile(
        "mma.sync.aligned.m16n8k16.row.col.f32.bf16.bf16.f32 "
        "{%0,%1,%2,%3}, {%4,%5,%6,%7}, {%8,%9}, {%0,%1,%2,%3};"
        : "+f"(c[0]), "+f"(c[1]), "+f"(c[2]), "+f"(c[3])
        : "r"(a[0]), "r"(a[1]), "r"(a[2]), "r"(a[3]), "r"(b[0]), "r"(b[1]));
}

__device__ __forceinline__ uint32_t pack_bf16(float a, float b) {
    __nv_bfloat16 x = __float2bfloat16(a), y = __float2bfloat16(b);
    return ((uint32_t)__bfloat16_as_ushort(y) << 16) | __bfloat16_as_ushort(x);
}

// =================== GEMM1: x @ W1, 2-pass (A exact, B bf16) ===============
// M x 256 x 128, CTA tile 128x128, 8 warps (4x2). D = Ahi*B + Alo*B.
__global__ __launch_bounds__(256, 1) void k_gemm1(
    const float* __restrict__ A, int M,
    const __nv_bfloat16* __restrict__ Bhi,
    uint32_t* __restrict__ Cb)
{
    constexpr int KDIM = 256, NDIM = 128, PAD = 72, NJT = 8;
    constexpr int A_HI = 0;
    constexpr int A_LO = 128 * PAD;
    constexpr int B_HI = 2 * 128 * PAD;
    // total bf16: 2*128*72 + 128*72 = 27648 -> 55296 bytes

    extern __shared__ __nv_bfloat16 sm[];
    const uint32_t sb = smem_u32(sm);

    const int tid  = threadIdx.x;
    const int wid  = tid >> 5;
    const int lane = tid & 31;
    const int wm = wid & 3;
    const int wn = wid >> 2;
    const int m_warp = wm * 32;
    const int n_warp = wn * 64;
    const int m0 = blockIdx.x * 128;

    float acc[2][NJT][4];
#pragma unroll
    for (int i = 0; i < 2; i++)
#pragma unroll
        for (int j = 0; j < NJT; j++)
#pragma unroll
            for (int q = 0; q < 4; q++) acc[i][j][q] = 0.f;

    const int a_off = (m_warp + (lane & 15)) * PAD + ((lane >> 4) << 3);
    const int b_off = (n_warp + (lane & 7) + ((lane >> 4) << 3)) * PAD
                    + (((lane >> 3) & 1) << 3);

    float4 areg[8];
    uint4  breg[4];
    #define LOAD_CHUNK(k0) do {                                               \
        _Pragma("unroll")                                                     \
        for (int t = 0; t < 8; t++) {                                         \
            int i = tid + t * 256;                                            \
            int m = i >> 4, q = i & 15;                                       \
            int rowg = m0 + m; if (rowg >= M) rowg = M - 1;                   \
            areg[t] = *(const float4*)(A + (size_t)rowg * KDIM + (k0) + q * 4); \
        }                                                                     \
        _Pragma("unroll")                                                     \
        for (int t = 0; t < 4; t++) {                                         \
            int i = tid + t * 256;                                            \
            int r = i >> 3, q = i & 7;                                        \
            breg[t] = *(const uint4*)(Bhi + (size_t)r * KDIM + (k0) + q * 8); \
        }                                                                     \
    } while (0)

    LOAD_CHUNK(0);

    for (int k0 = 0; k0 < KDIM; k0 += 64) {
#pragma unroll
        for (int t = 0; t < 8; t++) {
            int i = tid + t * 256;
            int m = i >> 4, q = i & 15;
            float4 v = areg[t];
            __nv_bfloat16 hx = __float2bfloat16(v.x), hy = __float2bfloat16(v.y);
            __nv_bfloat16 hz = __float2bfloat16(v.z), hw = __float2bfloat16(v.w);
            uint32_t hp0 = ((uint32_t)__bfloat16_as_ushort(hy) << 16) | __bfloat16_as_ushort(hx);
            uint32_t hp1 = ((uint32_t)__bfloat16_as_ushort(hw) << 16) | __bfloat16_as_ushort(hz);
            uint32_t lp0 = pack_bf16(v.x - __bfloat162float(hx), v.y - __bfloat162float(hy));
            uint32_t lp1 = pack_bf16(v.z - __bfloat162float(hz), v.w - __bfloat162float(hw));
            *(uint2*)(sm + A_HI + m * PAD + q * 4) = make_uint2(hp0, hp1);
            *(uint2*)(sm + A_LO + m * PAD + q * 4) = make_uint2(lp0, lp1);
        }
#pragma unroll
        for (int t = 0; t < 4; t++) {
            int i = tid + t * 256;
            int r = i >> 3, q = i & 7;
            *(uint4*)(sm + B_HI + r * PAD + q * 8) = breg[t];
        }
        __syncthreads();

        if (k0 + 64 < KDIM) LOAD_CHUNK(k0 + 64);

#pragma unroll
        for (int kk = 0; kk < 64; kk += 16) {
            uint32_t ah[2][4], al[2][4];
#pragma unroll
            for (int i = 0; i < 2; i++) {
                uint32_t base = (uint32_t)((a_off + i * 16 * PAD + kk) * 2);
                ldsm_x4(ah[i], sb + A_HI * 2 + base);
                ldsm_x4(al[i], sb + A_LO * 2 + base);
            }
            uint32_t bh[NJT][2];
#pragma unroll
            for (int jj = 0; jj < NJT / 2; jj++) {
                uint32_t base = (uint32_t)((b_off + jj * 16 * PAD + kk) * 2);
                uint32_t r[4];
                ldsm_x4(r, sb + B_HI * 2 + base);
                bh[2*jj][0] = r[0]; bh[2*jj][1] = r[1];
                bh[2*jj+1][0] = r[2]; bh[2*jj+1][1] = r[3];
            }
#pragma unroll
            for (int i = 0; i < 2; i++)
#pragma unroll
                for (int j = 0; j < NJT; j++) {
                    mma_bf16(acc[i][j], ah[i], bh[j]);
                    mma_bf16(acc[i][j], al[i], bh[j]);
                }
        }
        __syncthreads();
    }
    #undef LOAD_CHUNK

#pragma unroll
    for (int i = 0; i < 2; i++) {
        int r0 = m0 + m_warp + i * 16 + (lane >> 2);
#pragma unroll
        for (int j = 0; j < NJT; j++) {
            int col = n_warp + j * 8 + (lane & 3) * 2;
            if (r0 < M)
                Cb[(size_t)r0 * 64 + (col >> 1)] = pack_bf16(acc[i][j][0], acc[i][j][1]);
            if (r0 + 8 < M)
                Cb[(size_t)(r0 + 8) * 64 + (col >> 1)] = pack_bf16(acc[i][j][2], acc[i][j][3]);
        }
    }
}

// =================== GEMM2: hb(bf16) @ W2hi, single-pass mma ===============
// A exact bf16, B bf16-rounded. K=128 (single chunk), N=64, PAD2=136.
__global__ __launch_bounds__(256, 1) void k_gemm2(
    const uint32_t* __restrict__ Ab, int M,
    const __nv_bfloat16* __restrict__ Bhi,
    uint32_t* __restrict__ Cb)
{
    constexpr int KDIM = 128, NDIM = 64, PAD2 = 136, NJT = 4;
    constexpr int A_HI = 0;                    // 128 rows x 136
    constexpr int B_HI = 128 * PAD2;           // 17408
    // total bf16: 17408 + 64*136 = 26112 -> 52224 bytes

    extern __shared__ __nv_bfloat16 sm[];
    const uint32_t sb = smem_u32(sm);

    const int tid  = threadIdx.x;
    const int wid  = tid >> 5;
    const int lane = tid & 31;
    const int wm = wid & 3;
    const int wn = wid >> 2;
    const int m_warp = wm * 32;
    const int n_warp = wn * 32;
    const int m0 = blockIdx.x * 128;

    // ---- A fill: 128 rows x 16 uint4 -> 2048 uint4, 8 iters ----
#pragma unroll
    for (int t = 0; t < 8; t++) {
        int i = tid + t * 256;
        int r = i >> 4, q = i & 15;
        int rowg = m0 + r; if (rowg >= M) rowg = M - 1;
        uint4 v = *(const uint4*)(Ab + (size_t)rowg * 64 + q * 4);
        *(uint4*)(sm + A_HI + r * PAD2 + q * 8) = v;
    }
    // ---- B fill: 64 rows x 16 uint4 = 1024 uint4, 4 iters ----
#pragma unroll
    for (int t = 0; t < 4; t++) {
        int i = tid + t * 256;
        int r = i >> 4, q = i & 15;
        uint4 v = *(const uint4*)(Bhi + (size_t)r * KDIM + q * 8);
        *(uint4*)(sm + B_HI + r * PAD2 + q * 8) = v;
    }
    __syncthreads();

    float acc[2][NJT][4];
#pragma unroll
    for (int i = 0; i < 2; i++)
#pragma unroll
        for (int j = 0; j < NJT; j++)
#pragma unroll
            for (int q = 0; q < 4; q++) acc[i][j][q] = 0.f;

    const int a_off = (m_warp + (lane & 15)) * PAD2 + ((lane >> 4) << 3);
    const int b_off = (n_warp + (lane & 7) + ((lane >> 4) << 3)) * PAD2
                    + (((lane >> 3) & 1) << 3);

#pragma unroll
    for (int kk = 0; kk < KDIM; kk += 16) {
        uint32_t ah[2][4];
#pragma unroll
        for (int i = 0; i < 2; i++) {
            uint32_t base = (uint32_t)((a_off + i * 16 * PAD2 + kk) * 2);
            ldsm_x4(ah[i], sb + A_HI * 2 + base);
        }
        uint32_t bh[NJT][2];
#pragma unroll
        for (int jj = 0; jj < NJT / 2; jj++) {
            uint32_t base = (uint32_t)((b_off + jj * 16 * PAD2 + kk) * 2);
            uint32_t r[4];
            ldsm_x4(r, sb + B_HI * 2 + base);
            bh[2*jj][0] = r[0]; bh[2*jj][1] = r[1];
            bh[2*jj+1][0] = r[2]; bh[2*jj+1][1] = r[3];
        }
#pragma unroll
        for (int i = 0; i < 2; i++)
#pragma unroll
            for (int j = 0; j < NJT; j++)
                mma_bf16(acc[i][j], ah[i], bh[j]);
    }

    // epilogue: pack col pairs -> H2b (20 u32 per row, cols < 40)
#pragma unroll
    for (int i = 0; i < 2; i++) {
        int r0 = m0 + m_warp + i * 16 + (lane >> 2);
#pragma unroll
        for (int j = 0; j < NJT; j++) {
            int col = n_warp + j * 8 + (lane & 3) * 2;
            if (col < F_OUT) {
                if (r0 < M)
                    Cb[(size_t)r0 * 20 + (col >> 1)] = pack_bf16(acc[i][j][0], acc[i][j][1]);
                if (r0 + 8 < M)
                    Cb[(size_t)(r0 + 8) * 20 + (col >> 1)] = pack_bf16(acc[i][j][2], acc[i][j][3]);
            }
        }
    }
}

// bake W^T (N-major) bf16
__global__ void k_prep_b(const float* __restrict__ W, int K, int N, int nact,
                         __nv_bfloat16* __restrict__ hi) {
    int idx = blockIdx.x * blockDim.x + threadIdx.x;
    if (idx >= N * K) return;
    int n = idx / K, k = idx % K;
    float v = (n < nact) ? W[(size_t)k * nact + n] : 0.f;
    hi[idx] = __float2bfloat16(v);
}

// ---------------- preproc: dtype detect + deg init (fused) -----------------
__global__ void k_pre0(const unsigned* __restrict__ w) {
    int i = blockIdx.x * blockDim.x + threadIdx.x;
    if (i < N_NODES) g_deg[i] = 1;      // self loop
    if (blockIdx.x == 0) {
        __shared__ int any;
        if (threadIdx.x == 0) any = 0;
        __syncthreads();
        for (int j = threadIdx.x; j < 512; j += blockDim.x)
            if (w[2 * j + 1] != 0u) atomicOr(&any, 1);
        __syncthreads();
        if (threadIdx.x == 0) g_is64 = (any == 0);
    }
}

__global__ void k_convert(const void* __restrict__ ei) {
    int e = blockIdx.x * blockDim.x + threadIdx.x;
    if (e >= N_EDGES) return;
    int s, d;
    if (g_is64) {
        const long long* p = (const long long*)ei;
        s = (int)p[e];
        d = (int)p[N_EDGES + e];
    } else {
        const int* p = (const int*)ei;
        s = p[e];
        d = p[N_EDGES + e];
    }
    g_src[e] = s;
    g_dst[e] = d;
    atomicAdd(&g_deg[d], 1);
}

// ---------------- CSR build: 2-level scan (scan1 also emits dinv) ----------
__global__ void k_scan1() {
    __shared__ int sh[1024];
    int tid = threadIdx.x;
    int i = blockIdx.x * 1024 + tid;
    int v = (i < N_NODES) ? (g_deg[i] - 1) : 0;
    if (i < N_NODES) g_dinv[i] = rsqrtf((float)(v + 1));
    sh[tid] = v;
    __syncthreads();
    for (int off = 1; off < 1024; off <<= 1) {
        int t = (tid >= off) ? sh[tid - off] : 0;
        __syncthreads();
        sh[tid] += t;
        __syncthreads();
    }
    if (i < N_NODES) g_rowptr[i] = sh[tid] - v;   // exclusive
    if (tid == 1023) g_bsum[blockIdx.x] = sh[1023];
}

__global__ void k_scan2() {
    __shared__ int sh[128];
    int tid = threadIdx.x;
    int v = (tid < NSCAN_BLK) ? g_bsum[tid] : 0;
    sh[tid] = v;
    __syncthreads();
    for (int off = 1; off < 128; off <<= 1) {
        int t = (tid >= off) ? sh[tid - off] : 0;
        __syncthreads();
        sh[tid] += t;
        __syncthreads();
    }
    if (tid < NSCAN_BLK) g_bsum[tid] = sh[tid] - v;
}

__global__ void k_scan3() {
    int i = blockIdx.x * blockDim.x + threadIdx.x;
    if (i < N_NODES) {
        int r = g_rowptr[i] + g_bsum[i >> 10];
        g_rowptr[i] = r;
        g_cursor[i] = r;
    } else if (i == N_NODES) {
        g_rowptr[N_NODES] = N_EDGES;
    }
}

__global__ void k_scatter() {
    int e = blockIdx.x * blockDim.x + threadIdx.x;
    if (e >= N_EDGES) return;
    int d = g_dst[e];
    int p = atomicAdd(&g_cursor[d], 1);
    g_ssrc[p] = g_src[e];
}

// --------- layer-1 aggregation: warp per node, bf16 in / bf16 out ---------
__device__ __forceinline__ void acc_bf16row(float4& acc, float w, uint2 u) {
    __nv_bfloat162 p0 = *reinterpret_cast<__nv_bfloat162*>(&u.x);
    __nv_bfloat162 p1 = *reinterpret_cast<__nv_bfloat162*>(&u.y);
    acc.x += w * __low2float(p0);
    acc.y += w * __high2float(p0);
    acc.z += w * __low2float(p1);
    acc.w += w * __high2float(p1);
}

__global__ __launch_bounds__(256) void k_agg1(const float* __restrict__ b1) {
    int node = (blockIdx.x * blockDim.x + threadIdx.x) >> 5;
    if (node >= N_NODES) return;
    int lane = threadIdx.x & 31;
    float di = g_dinv[node];
    float wself = di * di;

    float4 acc = make_float4(0.f, 0.f, 0.f, 0.f);
    acc_bf16row(acc, wself, ((const uint2*)(g_H1b + (size_t)node * 64))[lane]);

    int beg = g_rowptr[node], end = g_rowptr[node + 1];
    for (int p0 = beg; p0 < end; p0 += 32) {
        int myp = p0 + lane;
        int s = (myp < end) ? g_ssrc[myp] : 0;
        float ws = (myp < end) ? g_dinv[s] * di : 0.f;
        int cnt = min(32, end - p0);
        int j = 0;
        for (; j + 4 <= cnt; j += 4) {
            int   s0 = __shfl_sync(0xffffffffu, s, j);
            int   s1 = __shfl_sync(0xffffffffu, s, j + 1);
            int   s2 = __shfl_sync(0xffffffffu, s, j + 2);
            int   s3 = __shfl_sync(0xffffffffu, s, j + 3);
            float w0 = __shfl_sync(0xffffffffu, ws, j);
            float w1 = __shfl_sync(0xffffffffu, ws, j + 1);
            float w2 = __shfl_sync(0xffffffffu, ws, j + 2);
            float w3 = __shfl_sync(0xffffffffu, ws, j + 3);
            uint2 u0 = ((const uint2*)(g_H1b + (size_t)s0 * 64))[lane];
            uint2 u1 = ((const uint2*)(g_H1b + (size_t)s1 * 64))[lane];
            uint2 u2 = ((const uint2*)(g_H1b + (size_t)s2 * 64))[lane];
            uint2 u3 = ((const uint2*)(g_H1b + (size_t)s3 * 64))[lane];
            acc_bf16row(acc, w0, u0);
            acc_bf16row(acc, w1, u1);
            acc_bf16row(acc, w2, u2);
            acc_bf16row(acc, w3, u3);
        }
        for (; j < cnt; ++j) {
            int   sj = __shfl_sync(0xffffffffu, s, j);
            float wj = __shfl_sync(0xffffffffu, ws, j);
            acc_bf16row(acc, wj, ((const uint2*)(g_H1b + (size_t)sj * 64))[lane]);
        }
    }
    float4 bb = ((const float4*)b1)[lane];
    acc.x = fmaxf(acc.x + bb.x, 0.f);
    acc.y = fmaxf(acc.y + bb.y, 0.f);
    acc.z = fmaxf(acc.z + bb.z, 0.f);
    acc.w = fmaxf(acc.w + bb.w, 0.f);
    uint2 packed = make_uint2(pack_bf16(acc.x, acc.y), pack_bf16(acc.z, acc.w));
    ((uint2*)(g_hb + (size_t)node * 64))[lane] = packed;
}

// ---- layer-2 aggregation (bf16 H2 gather) + bias + log_softmax ------------
__global__ __launch_bounds__(256) void k_agg2(const float* __restrict__ b2,
                                              float* __restrict__ out) {
    int node = (blockIdx.x * blockDim.x + threadIdx.x) >> 5;
    if (node >= N_NODES) return;
    int lane = threadIdx.x & 31;
    bool act = lane < 20;                  // 20 u32 = 40 cols
    float di = g_dinv[node];
    float wself = di * di;

    int llane = act ? lane : 0;            // clamp for safe addressing
    float acc0 = 0.f, acc1 = 0.f;          // cols 2*lane, 2*lane+1
    {
        uint32_t u = g_H2b[(size_t)node * 20 + llane];
        __nv_bfloat162 p = *reinterpret_cast<__nv_bfloat162*>(&u);
        acc0 = wself * __low2float(p);
        acc1 = wself * __high2float(p);
    }

    int beg = g_rowptr[node], end = g_rowptr[node + 1];
    for (int p0 = beg; p0 < end; p0 += 32) {
        int myp = p0 + lane;
        int s = (myp < end) ? g_ssrc[myp] : 0;
        float ws = (myp < end) ? g_dinv[s] * di : 0.f;
        int cnt = min(32, end - p0);
        int j = 0;
        for (; j + 4 <= cnt; j += 4) {
            int   s0 = __shfl_sync(0xffffffffu, s, j);
            int   s1 = __shfl_sync(0xffffffffu, s, j + 1);
            int   s2 = __shfl_sync(0xffffffffu, s, j + 2);
            int   s3 = __shfl_sync(0xffffffffu, s, j + 3);
            float w0 = __shfl_sync(0xffffffffu, ws, j);
            float w1 = __shfl_sync(0xffffffffu, ws, j + 1);
            float w2 = __shfl_sync(0xffffffffu, ws, j + 2);
            float w3 = __shfl_sync(0xffffffffu, ws, j + 3);
            uint32_t u0 = g_H2b[(size_t)s0 * 20 + llane];
            uint32_t u1 = g_H2b[(size_t)s1 * 20 + llane];
            uint32_t u2 = g_H2b[(size_t)s2 * 20 + llane];
            uint32_t u3 = g_H2b[(size_t)s3 * 20 + llane];
            __nv_bfloat162 q0 = *reinterpret_cast<__nv_bfloat162*>(&u0);
            __nv_bfloat162 q1 = *reinterpret_cast<__nv_bfloat162*>(&u1);
            __nv_bfloat162 q2 = *reinterpret_cast<__nv_bfloat162*>(&u2);
            __nv_bfloat162 q3 = *reinterpret_cast<__nv_bfloat162*>(&u3);
            acc0 += w0 * __low2float(q0) + w1 * __low2float(q1)
                  + w2 * __low2float(q2) + w3 * __low2float(q3);
            acc1 += w0 * __high2float(q0) + w1 * __high2float(q1)
                  + w2 * __high2float(q2) + w3 * __high2float(q3);
        }
        for (; j < cnt; ++j) {
            int   sj = __shfl_sync(0xffffffffu, s, j);
            float wj = __shfl_sync(0xffffffffu, ws, j);
            uint32_t u = g_H2b[(size_t)sj * 20 + llane];
            __nv_bfloat162 q = *reinterpret_cast<__nv_bfloat162*>(&u);
            acc0 += wj * __low2float(q);
            acc1 += wj * __high2float(q);
        }
    }
    acc0 += b2[2 * llane];
    acc1 += b2[2 * llane + 1];

    // warp log_softmax over 40 values (2 per active lane)
    float m = act ? fmaxf(acc0, acc1) : -1e30f;
#pragma unroll
    for (int o = 16; o; o >>= 1) m = fmaxf(m, __shfl_xor_sync(0xffffffffu, m, o));
    float e = act ? (expf(acc0 - m) + expf(acc1 - m)) : 0.f;
#pragma unroll
    for (int o = 16; o; o >>= 1) e += __shfl_xor_sync(0xffffffffu, e, o);
    float lse = m + logf(e);

    if (act) {
        float2 o2 = make_float2(acc0 - lse, acc1 - lse);
        *(float2*)(out + (size_t)node * F_OUT + 2 * lane) = o2;
    }
}

// ---------------- host launcher --------------------------------------------
extern "C" void kernel_launch(void* const* d_in, const int* in_sizes, int n_in,
                              void* d_out, int out_size) {
    const float* x  = (const float*)d_in[0];
    const void*  ei = d_in[1];
    const float* W1 = (const float*)d_in[2];
    const float* b1 = (const float*)d_in[3];
    const float* W2 = (const float*)d_in[4];
    const float* b2 = (const float*)d_in[5];
    float* out = (float*)d_out;

    uint32_t *dH1b, *dhb, *dH2b;
    __nv_bfloat16 *dB1hi, *dB2hi;
    cudaGetSymbolAddress((void**)&dH1b,  g_H1b);
    cudaGetSymbolAddress((void**)&dhb,   g_hb);
    cudaGetSymbolAddress((void**)&dH2b,  g_H2b);
    cudaGetSymbolAddress((void**)&dB1hi, g_B1hi);
    cudaGetSymbolAddress((void**)&dB2hi, g_B2hi);

    const int SMEM1 = (2 * 128 + 128) * 72 * 2;   // 55296
    const int SMEM2 = (128 + 64) * 136 * 2;       // 52224

    static cudaStream_t s2;
    static cudaEvent_t evFork, evJoin;
    static bool init_done = false;
    if (!init_done) {
        cudaFuncSetAttribute(k_gemm1,
                             cudaFuncAttributeMaxDynamicSharedMemorySize, SMEM1);
        cudaFuncSetAttribute(k_gemm2,
                             cudaFuncAttributeMaxDynamicSharedMemorySize, SMEM2);
        cudaStreamCreateWithFlags(&s2, cudaStreamNonBlocking);
        cudaEventCreateWithFlags(&evFork, cudaEventDisableTiming);
        cudaEventCreateWithFlags(&evJoin, cudaEventDisableTiming);
        init_done = true;
    }

    const int TB = 256;
    int nblkN = (N_NODES + TB - 1) / TB;
    int nblkE = (N_EDGES + TB - 1) / TB;
    int aggBlk = (N_NODES * 32) / TB;
    int gemmBlk = (N_NODES + 127) / 128;          // 782

    // ---- fork: side stream = weights + GEMM1; main stream = CSR build ----
    cudaEventRecord(evFork, 0);
    cudaStreamWaitEvent(s2, evFork, 0);

    k_prep_b<<<(128 * 256 + TB - 1) / TB, TB, 0, s2>>>(W1, 256, 128, 128, dB1hi);
    k_prep_b<<<(64 * 128 + TB - 1) / TB, TB, 0, s2>>>(W2, 128, 64, 40, dB2hi);
    k_gemm1<<<gemmBlk, 256, SMEM1, s2>>>(x, N_NODES, dB1hi, dH1b);

    k_pre0<<<nblkN, TB>>>((const unsigned*)ei);
    k_convert<<<nblkE, TB>>>(ei);
    k_scan1<<<NSCAN_BLK, 1024>>>();
    k_scan2<<<1, 128>>>();
    k_scan3<<<(N_NODES + 1 + TB - 1) / TB, TB>>>();
    k_scatter<<<nblkE, TB>>>();

    cudaEventRecord(evJoin, s2);
    cudaStreamWaitEvent(0, evJoin, 0);

    // agg1 (bf16 in/out), GEMM2 (1-pass), agg2 (bf16 gather) + log_softmax
    k_agg1<<<aggBlk, TB>>>(b1);
    k_gemm2<<<gemmBlk, 256, SMEM2>>>(dhb, N_NODES, dB2hi, dH2b);
    k_agg2<<<aggBlk, TB>>>(b2, out);
}

// round 10
// speedup vs baseline: 1.4965x; 1.0623x over previous
#include <cuda_runtime.h>
#include <cuda_bf16.h>
#include <math.h>
#include <stdint.h>

#define N_NODES 100000
#define N_EDGES 1600000
#define F_IN    256
#define F_HID   128
#define F_OUT   40
#define NSCAN_BLK 98            // ceil(100000/1024)

// ---------------- device scratch (static globals: allowed) ----------------
__device__ int   g_is64;
__device__ int   g_deg[N_NODES];
__device__ float g_dinv[N_NODES];
__device__ int   g_rowptr[N_NODES + 1];
__device__ int   g_cursor[N_NODES];
__device__ int   g_src[N_EDGES];
__device__ int   g_dst[N_EDGES];
__device__ int   g_ssrc[N_EDGES];       // src ids sorted by dst
__device__ int   g_bsum[NSCAN_BLK];
__device__ uint32_t g_H1b[(size_t)N_NODES * 64];   // x @ W1, packed bf16x2
__device__ uint32_t g_hb [(size_t)N_NODES * 64];   // relu(agg1+b1), packed bf16x2
__device__ uint32_t g_H2b[(size_t)N_NODES * 20];   // h @ W2, packed bf16x2
// W^T baked as N-major bf16: [N][K]
__device__ __align__(16) __nv_bfloat16 g_B1hi[128 * 256];
__device__ __align__(16) __nv_bfloat16 g_B2hi[64 * 128];

// ======================= mma.sync helpers ==================================
__device__ __forceinline__ uint32_t smem_u32(const void* p) {
    uint32_t a;
    asm("{ .reg .u64 t; cvta.to.shared.u64 t, %1; cvt.u32.u64 %0, t; }"
        : "=r"(a) : "l"(p));
    return a;
}

__device__ __forceinline__ void ldsm_x4(uint32_t* r, uint32_t addr) {
    asm volatile("ldmatrix.sync.aligned.m8n8.x4.shared.b16 {%0,%1,%2,%3}, [%4];"
                 : "=r"(r[0]), "=r"(r[1]), "=r"(r[2]), "=r"(r[3]) : "r"(addr));
}

__device__ __forceinline__ void mma_bf16(float* c, const uint32_t* a, const uint32_t* b) {
    asm volatile(
        "mma.sync.aligned.m16n8k16.row.col.f32.bf16.bf16.f32 "
        "{%0,%1,%2,%3}, {%4,%5,%6,%7}, {%8,%9}, {%0,%1,%2,%3};"
        : "+f"(c[0]), "+f"(c[1]), "+f"(c[2]), "+f"(c[3])
        : "r"(a[0]), "r"(a[1]), "r"(a[2]), "r"(a[3]), "r"(b[0]), "r"(b[1]));
}

__device__ __forceinline__ uint32_t pack_bf16(float a, float b) {
    __nv_bfloat16 x = __float2bfloat16(a), y = __float2bfloat16(b);
    return ((uint32_t)__bfloat16_as_ushort(y) << 16) | __bfloat16_as_ushort(x);
}

// =================== GEMM1: x @ W1, single-pass bf16 =======================
// M x 256 x 128, CTA tile 128x128, 8 warps (4x2). A and B both bf16-rounded.
__global__ __launch_bounds__(256) void k_gemm1(
    const float* __restrict__ A, int M,
    const __nv_bfloat16* __restrict__ Bhi,
    uint32_t* __restrict__ Cb)
{
    constexpr int KDIM = 256, NDIM = 128, PAD = 72, NJT = 8;
    constexpr int A_HI = 0;
    constexpr int B_HI = 128 * PAD;
    // total bf16: 128*72 + 128*72 = 18432 -> 36864 bytes

    extern __shared__ __nv_bfloat16 sm[];
    const uint32_t sb = smem_u32(sm);

    const int tid  = threadIdx.x;
    const int wid  = tid >> 5;
    const int lane = tid & 31;
    const int wm = wid & 3;
    const int wn = wid >> 2;
    const int m_warp = wm * 32;
    const int n_warp = wn * 64;
    const int m0 = blockIdx.x * 128;

    float acc[2][NJT][4];
#pragma unroll
    for (int i = 0; i < 2; i++)
#pragma unroll
        for (int j = 0; j < NJT; j++)
#pragma unroll
            for (int q = 0; q < 4; q++) acc[i][j][q] = 0.f;

    const int a_off = (m_warp + (lane & 15)) * PAD + ((lane >> 4) << 3);
    const int b_off = (n_warp + (lane & 7) + ((lane >> 4) << 3)) * PAD
                    + (((lane >> 3) & 1) << 3);

    float4 areg[8];
    uint4  breg[4];
    #define LOAD_CHUNK(k0) do {                                               \
        _Pragma("unroll")                                                     \
        for (int t = 0; t < 8; t++) {                                         \
            int i = tid + t * 256;                                            \
            int m = i >> 4, q = i & 15;                                       \
            int rowg = m0 + m; if (rowg >= M) rowg = M - 1;                   \
            areg[t] = *(const float4*)(A + (size_t)rowg * KDIM + (k0) + q * 4); \
        }                                                                     \
        _Pragma("unroll")                                                     \
        for (int t = 0; t < 4; t++) {                                         \
            int i = tid + t * 256;                                            \
            int r = i >> 3, q = i & 7;                                        \
            breg[t] = *(const uint4*)(Bhi + (size_t)r * KDIM + (k0) + q * 8); \
        }                                                                     \
    } while (0)

    LOAD_CHUNK(0);

    for (int k0 = 0; k0 < KDIM; k0 += 64) {
#pragma unroll
        for (int t = 0; t < 8; t++) {
            int i = tid + t * 256;
            int m = i >> 4, q = i & 15;
            float4 v = areg[t];
            *(uint2*)(sm + A_HI + m * PAD + q * 4) =
                make_uint2(pack_bf16(v.x, v.y), pack_bf16(v.z, v.w));
        }
#pragma unroll
        for (int t = 0; t < 4; t++) {
            int i = tid + t * 256;
            int r = i >> 3, q = i & 7;
            *(uint4*)(sm + B_HI + r * PAD + q * 8) = breg[t];
        }
        __syncthreads();

        if (k0 + 64 < KDIM) LOAD_CHUNK(k0 + 64);

#pragma unroll
        for (int kk = 0; kk < 64; kk += 16) {
            uint32_t ah[2][4];
#pragma unroll
            for (int i = 0; i < 2; i++) {
                uint32_t base = (uint32_t)((a_off + i * 16 * PAD + kk) * 2);
                ldsm_x4(ah[i], sb + A_HI * 2 + base);
            }
            uint32_t bh[NJT][2];
#pragma unroll
            for (int jj = 0; jj < NJT / 2; jj++) {
                uint32_t base = (uint32_t)((b_off + jj * 16 * PAD + kk) * 2);
                uint32_t r[4];
                ldsm_x4(r, sb + B_HI * 2 + base);
                bh[2*jj][0] = r[0]; bh[2*jj][1] = r[1];
                bh[2*jj+1][0] = r[2]; bh[2*jj+1][1] = r[3];
            }
#pragma unroll
            for (int i = 0; i < 2; i++)
#pragma unroll
                for (int j = 0; j < NJT; j++)
                    mma_bf16(acc[i][j], ah[i], bh[j]);
        }
        __syncthreads();
    }
    #undef LOAD_CHUNK

#pragma unroll
    for (int i = 0; i < 2; i++) {
        int r0 = m0 + m_warp + i * 16 + (lane >> 2);
#pragma unroll
        for (int j = 0; j < NJT; j++) {
            int col = n_warp + j * 8 + (lane & 3) * 2;
            if (r0 < M)
                Cb[(size_t)r0 * 64 + (col >> 1)] = pack_bf16(acc[i][j][0], acc[i][j][1]);
            if (r0 + 8 < M)
                Cb[(size_t)(r0 + 8) * 64 + (col >> 1)] = pack_bf16(acc[i][j][2], acc[i][j][3]);
        }
    }
}

// =================== GEMM2: hb(bf16) @ W2hi, single-pass mma ===============
__global__ __launch_bounds__(256) void k_gemm2(
    const uint32_t* __restrict__ Ab, int M,
    const __nv_bfloat16* __restrict__ Bhi,
    uint32_t* __restrict__ Cb)
{
    constexpr int KDIM = 128, NDIM = 64, PAD2 = 136, NJT = 4;
    constexpr int A_HI = 0;                    // 128 rows x 136
    constexpr int B_HI = 128 * PAD2;           // 17408
    // total bf16: 17408 + 64*136 = 26112 -> 52224 bytes

    extern __shared__ __nv_bfloat16 sm[];
    const uint32_t sb = smem_u32(sm);

    const int tid  = threadIdx.x;
    const int wid  = tid >> 5;
    const int lane = tid & 31;
    const int wm = wid & 3;
    const int wn = wid >> 2;
    const int m_warp = wm * 32;
    const int n_warp = wn * 32;
    const int m0 = blockIdx.x * 128;

#pragma unroll
    for (int t = 0; t < 8; t++) {
        int i = tid + t * 256;
        int r = i >> 4, q = i & 15;
        int rowg = m0 + r; if (rowg >= M) rowg = M - 1;
        uint4 v = *(const uint4*)(Ab + (size_t)rowg * 64 + q * 4);
        *(uint4*)(sm + A_HI + r * PAD2 + q * 8) = v;
    }
#pragma unroll
    for (int t = 0; t < 4; t++) {
        int i = tid + t * 256;
        int r = i >> 4, q = i & 15;
        uint4 v = *(const uint4*)(Bhi + (size_t)r * KDIM + q * 8);
        *(uint4*)(sm + B_HI + r * PAD2 + q * 8) = v;
    }
    __syncthreads();

    float acc[2][NJT][4];
#pragma unroll
    for (int i = 0; i < 2; i++)
#pragma unroll
        for (int j = 0; j < NJT; j++)
#pragma unroll
            for (int q = 0; q < 4; q++) acc[i][j][q] = 0.f;

    const int a_off = (m_warp + (lane & 15)) * PAD2 + ((lane >> 4) << 3);
    const int b_off = (n_warp + (lane & 7) + ((lane >> 4) << 3)) * PAD2
                    + (((lane >> 3) & 1) << 3);

#pragma unroll
    for (int kk = 0; kk < KDIM; kk += 16) {
        uint32_t ah[2][4];
#pragma unroll
        for (int i = 0; i < 2; i++) {
            uint32_t base = (uint32_t)((a_off + i * 16 * PAD2 + kk) * 2);
            ldsm_x4(ah[i], sb + A_HI * 2 + base);
        }
        uint32_t bh[NJT][2];
#pragma unroll
        for (int jj = 0; jj < NJT / 2; jj++) {
            uint32_t base = (uint32_t)((b_off + jj * 16 * PAD2 + kk) * 2);
            uint32_t r[4];
            ldsm_x4(r, sb + B_HI * 2 + base);
            bh[2*jj][0] = r[0]; bh[2*jj][1] = r[1];
            bh[2*jj+1][0] = r[2]; bh[2*jj+1][1] = r[3];
        }
#pragma unroll
        for (int i = 0; i < 2; i++)
#pragma unroll
            for (int j = 0; j < NJT; j++)
                mma_bf16(acc[i][j], ah[i], bh[j]);
    }

#pragma unroll
    for (int i = 0; i < 2; i++) {
        int r0 = m0 + m_warp + i * 16 + (lane >> 2);
#pragma unroll
        for (int j = 0; j < NJT; j++) {
            int col = n_warp + j * 8 + (lane & 3) * 2;
            if (col < F_OUT) {
                if (r0 < M)
                    Cb[(size_t)r0 * 20 + (col >> 1)] = pack_bf16(acc[i][j][0], acc[i][j][1]);
                if (r0 + 8 < M)
                    Cb[(size_t)(r0 + 8) * 20 + (col >> 1)] = pack_bf16(acc[i][j][2], acc[i][j][3]);
            }
        }
    }
}

// bake W^T (N-major) bf16
__global__ void k_prep_b(const float* __restrict__ W, int K, int N, int nact,
                         __nv_bfloat16* __restrict__ hi) {
    int idx = blockIdx.x * blockDim.x + threadIdx.x;
    if (idx >= N * K) return;
    int n = idx / K, k = idx % K;
    float v = (n < nact) ? W[(size_t)k * nact + n] : 0.f;
    hi[idx] = __float2bfloat16(v);
}

// ---------------- preproc: dtype detect + deg init (fused) -----------------
__global__ void k_pre0(const unsigned* __restrict__ w) {
    int i = blockIdx.x * blockDim.x + threadIdx.x;
    if (i < N_NODES) g_deg[i] = 1;      // self loop
    if (blockIdx.x == 0) {
        __shared__ int any;
        if (threadIdx.x == 0) any = 0;
        __syncthreads();
        for (int j = threadIdx.x; j < 512; j += blockDim.x)
            if (w[2 * j + 1] != 0u) atomicOr(&any, 1);
        __syncthreads();
        if (threadIdx.x == 0) g_is64 = (any == 0);
    }
}

// 2 edges per thread, vectorized reads
__global__ void k_convert(const void* __restrict__ ei) {
    int e2 = (blockIdx.x * blockDim.x + threadIdx.x) * 2;
    if (e2 >= N_EDGES) return;
    int s0, d0, s1, d1;
    if (g_is64) {
        const longlong2* ps = (const longlong2*)((const long long*)ei + e2);
        const longlong2* pd = (const longlong2*)((const long long*)ei + N_EDGES + e2);
        longlong2 sv = *ps, dv = *pd;
        s0 = (int)sv.x; s1 = (int)sv.y;
        d0 = (int)dv.x; d1 = (int)dv.y;
    } else {
        const int2* ps = (const int2*)((const int*)ei + e2);
        const int2* pd = (const int2*)((const int*)ei + N_EDGES + e2);
        int2 sv = *ps, dv = *pd;
        s0 = sv.x; s1 = sv.y;
        d0 = dv.x; d1 = dv.y;
    }
    *(int2*)(g_src + e2) = make_int2(s0, s1);
    *(int2*)(g_dst + e2) = make_int2(d0, d1);
    atomicAdd(&g_deg[d0], 1);
    atomicAdd(&g_deg[d1], 1);
}

// ---------------- CSR build: 2-level scan (scan1 also emits dinv) ----------
__global__ void k_scan1() {
    __shared__ int sh[1024];
    int tid = threadIdx.x;
    int i = blockIdx.x * 1024 + tid;
    int v = (i < N_NODES) ? (g_deg[i] - 1) : 0;
    if (i < N_NODES) g_dinv[i] = rsqrtf((float)(v + 1));
    sh[tid] = v;
    __syncthreads();
    for (int off = 1; off < 1024; off <<= 1) {
        int t = (tid >= off) ? sh[tid - off] : 0;
        __syncthreads();
        sh[tid] += t;
        __syncthreads();
    }
    if (i < N_NODES) g_rowptr[i] = sh[tid] - v;   // exclusive
    if (tid == 1023) g_bsum[blockIdx.x] = sh[1023];
}

__global__ void k_scan2() {
    __shared__ int sh[128];
    int tid = threadIdx.x;
    int v = (tid < NSCAN_BLK) ? g_bsum[tid] : 0;
    sh[tid] = v;
    __syncthreads();
    for (int off = 1; off < 128; off <<= 1) {
        int t = (tid >= off) ? sh[tid - off] : 0;
        __syncthreads();
        sh[tid] += t;
        __syncthreads();
    }
    if (tid < NSCAN_BLK) g_bsum[tid] = sh[tid] - v;
}

__global__ void k_scan3() {
    int i = blockIdx.x * blockDim.x + threadIdx.x;
    if (i < N_NODES) {
        int r = g_rowptr[i] + g_bsum[i >> 10];
        g_rowptr[i] = r;
        g_cursor[i] = r;
    } else if (i == N_NODES) {
        g_rowptr[N_NODES] = N_EDGES;
    }
}

// 2 edges per thread
__global__ void k_scatter() {
    int e2 = (blockIdx.x * blockDim.x + threadIdx.x) * 2;
    if (e2 >= N_EDGES) return;
    int2 sv = *(const int2*)(g_src + e2);
    int2 dv = *(const int2*)(g_dst + e2);
    int p0 = atomicAdd(&g_cursor[dv.x], 1);
    g_ssrc[p0] = sv.x;
    int p1 = atomicAdd(&g_cursor[dv.y], 1);
    g_ssrc[p1] = sv.y;
}

// --------- layer-1 aggregation: warp per node, bf16 in / bf16 out ---------
__device__ __forceinline__ void acc_bf16row(float4& acc, float w, uint2 u) {
    __nv_bfloat162 p0 = *reinterpret_cast<__nv_bfloat162*>(&u.x);
    __nv_bfloat162 p1 = *reinterpret_cast<__nv_bfloat162*>(&u.y);
    acc.x += w * __low2float(p0);
    acc.y += w * __high2float(p0);
    acc.z += w * __low2float(p1);
    acc.w += w * __high2float(p1);
}

__global__ __launch_bounds__(256) void k_agg1(const float* __restrict__ b1) {
    int node = (blockIdx.x * blockDim.x + threadIdx.x) >> 5;
    if (node >= N_NODES) return;
    int lane = threadIdx.x & 31;
    float di = g_dinv[node];
    float wself = di * di;

    float4 acc = make_float4(0.f, 0.f, 0.f, 0.f);
    acc_bf16row(acc, wself, ((const uint2*)(g_H1b + (size_t)node * 64))[lane]);

    int beg = g_rowptr[node], end = g_rowptr[node + 1];
    for (int p0 = beg; p0 < end; p0 += 32) {
        int myp = p0 + lane;
        int s = (myp < end) ? g_ssrc[myp] : 0;
        float ws = (myp < end) ? g_dinv[s] * di : 0.f;
        int cnt = min(32, end - p0);
        int j = 0;
        for (; j + 4 <= cnt; j += 4) {
            int   s0 = __shfl_sync(0xffffffffu, s, j);
            int   s1 = __shfl_sync(0xffffffffu, s, j + 1);
            int   s2 = __shfl_sync(0xffffffffu, s, j + 2);
            int   s3 = __shfl_sync(0xffffffffu, s, j + 3);
            float w0 = __shfl_sync(0xffffffffu, ws, j);
            float w1 = __shfl_sync(0xffffffffu, ws, j + 1);
            float w2 = __shfl_sync(0xffffffffu, ws, j + 2);
            float w3 = __shfl_sync(0xffffffffu, ws, j + 3);
            uint2 u0 = ((const uint2*)(g_H1b + (size_t)s0 * 64))[lane];
            uint2 u1 = ((const uint2*)(g_H1b + (size_t)s1 * 64))[lane];
            uint2 u2 = ((const uint2*)(g_H1b + (size_t)s2 * 64))[lane];
            uint2 u3 = ((const uint2*)(g_H1b + (size_t)s3 * 64))[lane];
            acc_bf16row(acc, w0, u0);
            acc_bf16row(acc, w1, u1);
            acc_bf16row(acc, w2, u2);
            acc_bf16row(acc, w3, u3);
        }
        for (; j < cnt; ++j) {
            int   sj = __shfl_sync(0xffffffffu, s, j);
            float wj = __shfl_sync(0xffffffffu, ws, j);
            acc_bf16row(acc, wj, ((const uint2*)(g_H1b + (size_t)sj * 64))[lane]);
        }
    }
    float4 bb = ((const float4*)b1)[lane];
    acc.x = fmaxf(acc.x + bb.x, 0.f);
    acc.y = fmaxf(acc.y + bb.y, 0.f);
    acc.z = fmaxf(acc.z + bb.z, 0.f);
    acc.w = fmaxf(acc.w + bb.w, 0.f);
    uint2 packed = make_uint2(pack_bf16(acc.x, acc.y), pack_bf16(acc.z, acc.w));
    ((uint2*)(g_hb + (size_t)node * 64))[lane] = packed;
}

// ---- layer-2 aggregation (bf16 H2 gather) + bias + log_softmax ------------
__global__ __launch_bounds__(256) void k_agg2(const float* __restrict__ b2,
                                              float* __restrict__ out) {
    int node = (blockIdx.x * blockDim.x + threadIdx.x) >> 5;
    if (node >= N_NODES) return;
    int lane = threadIdx.x & 31;
    bool act = lane < 20;                  // 20 u32 = 40 cols
    float di = g_dinv[node];
    float wself = di * di;

    int llane = act ? lane : 0;            // clamp for safe addressing
    float acc0 = 0.f, acc1 = 0.f;          // cols 2*lane, 2*lane+1
    {
        uint32_t u = g_H2b[(size_t)node * 20 + llane];
        __nv_bfloat162 p = *reinterpret_cast<__nv_bfloat162*>(&u);
        acc0 = wself * __low2float(p);
        acc1 = wself * __high2float(p);
    }

    int beg = g_rowptr[node], end = g_rowptr[node + 1];
    for (int p0 = beg; p0 < end; p0 += 32) {
        int myp = p0 + lane;
        int s = (myp < end) ? g_ssrc[myp] : 0;
        float ws = (myp < end) ? g_dinv[s] * di : 0.f;
        int cnt = min(32, end - p0);
        int j = 0;
        for (; j + 4 <= cnt; j += 4) {
            int   s0 = __shfl_sync(0xffffffffu, s, j);
            int   s1 = __shfl_sync(0xffffffffu, s, j + 1);
            int   s2 = __shfl_sync(0xffffffffu, s, j + 2);
            int   s3 = __shfl_sync(0xffffffffu, s, j + 3);
            float w0 = __shfl_sync(0xffffffffu, ws, j);
            float w1 = __shfl_sync(0xffffffffu, ws, j + 1);
            float w2 = __shfl_sync(0xffffffffu, ws, j + 2);
            float w3 = __shfl_sync(0xffffffffu, ws, j + 3);
            uint32_t u0 = g_H2b[(size_t)s0 * 20 + llane];
            uint32_t u1 = g_H2b[(size_t)s1 * 20 + llane];
            uint32_t u2 = g_H2b[(size_t)s2 * 20 + llane];
            uint32_t u3 = g_H2b[(size_t)s3 * 20 + llane];
            __nv_bfloat162 q0 = *reinterpret_cast<__nv_bfloat162*>(&u0);
            __nv_bfloat162 q1 = *reinterpret_cast<__nv_bfloat162*>(&u1);
            __nv_bfloat162 q2 = *reinterpret_cast<__nv_bfloat162*>(&u2);
            __nv_bfloat162 q3 = *reinterpret_cast<__nv_bfloat162*>(&u3);
            acc0 += w0 * __low2float(q0) + w1 * __low2float(q1)
                  + w2 * __low2float(q2) + w3 * __low2float(q3);
            acc1 += w0 * __high2float(q0) + w1 * __high2float(q1)
                  + w2 * __high2float(q2) + w3 * __high2float(q3);
        }
        for (; j < cnt; ++j) {
            int   sj = __shfl_sync(0xffffffffu, s, j);
            float wj = __shfl_sync(0xffffffffu, ws, j);
            uint32_t u = g_H2b[(size_t)sj * 20 + llane];
            __nv_bfloat162 q = *reinterpret_cast<__nv_bfloat162*>(&u);
            acc0 += wj * __low2float(q);
            acc1 += wj * __high2float(q);
        }
    }
    acc0 += b2[2 * llane];
    acc1 += b2[2 * llane + 1];

    float m = act ? fmaxf(acc0, acc1) : -1e30f;
#pragma unroll
    for (int o = 16; o; o >>= 1) m = fmaxf(m, __shfl_xor_sync(0xffffffffu, m, o));
    float e = act ? (expf(acc0 - m) + expf(acc1 - m)) : 0.f;
#pragma unroll
    for (int o = 16; o; o >>= 1) e += __shfl_xor_sync(0xffffffffu, e, o);
    float lse = m + logf(e);

    if (act) {
        float2 o2 = make_float2(acc0 - lse, acc1 - lse);
        *(float2*)(out + (size_t)node * F_OUT + 2 * lane) = o2;
    }
}

// ---------------- host launcher --------------------------------------------
extern "C" void kernel_launch(void* const* d_in, const int* in_sizes, int n_in,
                              void* d_out, int out_size) {
    const float* x  = (const float*)d_in[0];
    const void*  ei = d_in[1];
    const float* W1 = (const float*)d_in[2];
    const float* b1 = (const float*)d_in[3];
    const float* W2 = (const float*)d_in[4];
    const float* b2 = (const float*)d_in[5];
    float* out = (float*)d_out;

    uint32_t *dH1b, *dhb, *dH2b;
    __nv_bfloat16 *dB1hi, *dB2hi;
    cudaGetSymbolAddress((void**)&dH1b,  g_H1b);
    cudaGetSymbolAddress((void**)&dhb,   g_hb);
    cudaGetSymbolAddress((void**)&dH2b,  g_H2b);
    cudaGetSymbolAddress((void**)&dB1hi, g_B1hi);
    cudaGetSymbolAddress((void**)&dB2hi, g_B2hi);

    const int SMEM1 = (128 + 128) * 72 * 2;       // 36864
    const int SMEM2 = (128 + 64) * 136 * 2;       // 52224

    static cudaStream_t s2;
    static cudaEvent_t evFork, evJoin;
    static bool init_done = false;
    if (!init_done) {
        cudaFuncSetAttribute(k_gemm1,
                             cudaFuncAttributeMaxDynamicSharedMemorySize, SMEM1);
        cudaFuncSetAttribute(k_gemm2,
                             cudaFuncAttributeMaxDynamicSharedMemorySize, SMEM2);
        cudaStreamCreateWithFlags(&s2, cudaStreamNonBlocking);
        cudaEventCreateWithFlags(&evFork, cudaEventDisableTiming);
        cudaEventCreateWithFlags(&evJoin, cudaEventDisableTiming);
        init_done = true;
    }

    const int TB = 256;
    int nblkN = (N_NODES + TB - 1) / TB;
    int nblkE2 = (N_EDGES / 2 + TB - 1) / TB;     // 3125 (2 edges/thread)
    int aggBlk = (N_NODES * 32) / TB;
    int gemmBlk = (N_NODES + 127) / 128;          // 782

    // ---- fork: side stream = weights + GEMM1; main stream = CSR build ----
    cudaEventRecord(evFork, 0);
    cudaStreamWaitEvent(s2, evFork, 0);

    k_prep_b<<<(128 * 256 + TB - 1) / TB, TB, 0, s2>>>(W1, 256, 128, 128, dB1hi);
    k_prep_b<<<(64 * 128 + TB - 1) / TB, TB, 0, s2>>>(W2, 128, 64, 40, dB2hi);
    k_gemm1<<<gemmBlk, 256, SMEM1, s2>>>(x, N_NODES, dB1hi, dH1b);

    k_pre0<<<nblkN, TB>>>((const unsigned*)ei);
    k_convert<<<nblkE2, TB>>>(ei);
    k_scan1<<<NSCAN_BLK, 1024>>>();
    k_scan2<<<1, 128>>>();
    k_scan3<<<(N_NODES + 1 + TB - 1) / TB, TB>>>();
    k_scatter<<<nblkE2, TB>>>();

    cudaEventRecord(evJoin, s2);
    cudaStreamWaitEvent(0, evJoin, 0);

    // agg1 (bf16 in/out), GEMM2 (1-pass), agg2 (bf16 gather) + log_softmax
    k_agg1<<<aggBlk, TB>>>(b1);
    k_gemm2<<<gemmBlk, 256, SMEM2>>>(dhb, N_NODES, dB2hi, dH2b);
    k_agg2<<<aggBlk, TB>>>(b2, out);
}

// round 11
// speedup vs baseline: 1.5104x; 1.0093x over previous
#include <cuda_runtime.h>
#include <cuda_bf16.h>
#include <math.h>
#include <stdint.h>

#define N_NODES 100000
#define N_EDGES 1600000
#define F_IN    256
#define F_HID   128
#define F_OUT   40

// ---------------- device scratch (static globals: allowed) ----------------
__device__ int   g_is64;
__device__ int   g_total;               // CSR allocation counter (zeroed by k_detect)
__device__ int   g_deg[N_NODES];        // zero-init; self-resets in k_alloc
__device__ float g_dinv[N_NODES];
__device__ int   g_rowptr[N_NODES];
__device__ int   g_rend[N_NODES];
__device__ int   g_cursor[N_NODES];
__device__ int   g_src[N_EDGES];
__device__ int   g_dst[N_EDGES];
__device__ int   g_ssrc[N_EDGES];       // src ids grouped by dst segment
__device__ uint32_t g_H1b[(size_t)N_NODES * 64];   // x @ W1, packed bf16x2
__device__ uint32_t g_hb [(size_t)N_NODES * 64];   // relu(agg1+b1), packed bf16x2
__device__ uint32_t g_H2b[(size_t)N_NODES * 20];   // h @ W2, packed bf16x2
// W^T baked as N-major bf16: [N][K]
__device__ __align__(16) __nv_bfloat16 g_B1hi[128 * 256];
__device__ __align__(16) __nv_bfloat16 g_B2hi[64 * 128];

// ======================= mma.sync helpers ==================================
__device__ __forceinline__ uint32_t smem_u32(const void* p) {
    uint32_t a;
    asm("{ .reg .u64 t; cvta.to.shared.u64 t, %1; cvt.u32.u64 %0, t; }"
        : "=r"(a) : "l"(p));
    return a;
}

__device__ __forceinline__ void ldsm_x4(uint32_t* r, uint32_t addr) {
    asm volatile("ldmatrix.sync.aligned.m8n8.x4.shared.b16 {%0,%1,%2,%3}, [%4];"
                 : "=r"(r[0]), "=r"(r[1]), "=r"(r[2]), "=r"(r[3]) : "r"(addr));
}

__device__ __forceinline__ void mma_bf16(float* c, const uint32_t* a, const uint32_t* b) {
    asm volatile(
        "mma.sync.aligned.m16n8k16.row.col.f32.bf16.bf16.f32 "
        "{%0,%1,%2,%3}, {%4,%5,%6,%7}, {%8,%9}, {%0,%1,%2,%3};"
        : "+f"(c[0]), "+f"(c[1]), "+f"(c[2]), "+f"(c[3])
        : "r"(a[0]), "r"(a[1]), "r"(a[2]), "r"(a[3]), "r"(b[0]), "r"(b[1]));
}

__device__ __forceinline__ uint32_t pack_bf16(float a, float b) {
    __nv_bfloat16 x = __float2bfloat16(a), y = __float2bfloat16(b);
    return ((uint32_t)__bfloat16_as_ushort(y) << 16) | __bfloat16_as_ushort(x);
}

// =================== GEMM1: x @ W1, single-pass bf16 =======================
__global__ __launch_bounds__(256) void k_gemm1(
    const float* __restrict__ A, int M,
    const __nv_bfloat16* __restrict__ Bhi,
    uint32_t* __restrict__ Cb)
{
    constexpr int KDIM = 256, NDIM = 128, PAD = 72, NJT = 8;
    constexpr int A_HI = 0;
    constexpr int B_HI = 128 * PAD;

    extern __shared__ __nv_bfloat16 sm[];
    const uint32_t sb = smem_u32(sm);

    const int tid  = threadIdx.x;
    const int wid  = tid >> 5;
    const int lane = tid & 31;
    const int wm = wid & 3;
    const int wn = wid >> 2;
    const int m_warp = wm * 32;
    const int n_warp = wn * 64;
    const int m0 = blockIdx.x * 128;

    float acc[2][NJT][4];
#pragma unroll
    for (int i = 0; i < 2; i++)
#pragma unroll
        for (int j = 0; j < NJT; j++)
#pragma unroll
            for (int q = 0; q < 4; q++) acc[i][j][q] = 0.f;

    const int a_off = (m_warp + (lane & 15)) * PAD + ((lane >> 4) << 3);
    const int b_off = (n_warp + (lane & 7) + ((lane >> 4) << 3)) * PAD
                    + (((lane >> 3) & 1) << 3);

    float4 areg[8];
    uint4  breg[4];
    #define LOAD_CHUNK(k0) do {                                               \
        _Pragma("unroll")                                                     \
        for (int t = 0; t < 8; t++) {                                         \
            int i = tid + t * 256;                                            \
            int m = i >> 4, q = i & 15;                                       \
            int rowg = m0 + m; if (rowg >= M) rowg = M - 1;                   \
            areg[t] = *(const float4*)(A + (size_t)rowg * KDIM + (k0) + q * 4); \
        }                                                                     \
        _Pragma("unroll")                                                     \
        for (int t = 0; t < 4; t++) {                                         \
            int i = tid + t * 256;                                            \
            int r = i >> 3, q = i & 7;                                        \
            breg[t] = *(const uint4*)(Bhi + (size_t)r * KDIM + (k0) + q * 8); \
        }                                                                     \
    } while (0)

    LOAD_CHUNK(0);

    for (int k0 = 0; k0 < KDIM; k0 += 64) {
#pragma unroll
        for (int t = 0; t < 8; t++) {
            int i = tid + t * 256;
            int m = i >> 4, q = i & 15;
            float4 v = areg[t];
            *(uint2*)(sm + A_HI + m * PAD + q * 4) =
                make_uint2(pack_bf16(v.x, v.y), pack_bf16(v.z, v.w));
        }
#pragma unroll
        for (int t = 0; t < 4; t++) {
            int i = tid + t * 256;
            int r = i >> 3, q = i & 7;
            *(uint4*)(sm + B_HI + r * PAD + q * 8) = breg[t];
        }
        __syncthreads();

        if (k0 + 64 < KDIM) LOAD_CHUNK(k0 + 64);

#pragma unroll
        for (int kk = 0; kk < 64; kk += 16) {
            uint32_t ah[2][4];
#pragma unroll
            for (int i = 0; i < 2; i++) {
                uint32_t base = (uint32_t)((a_off + i * 16 * PAD + kk) * 2);
                ldsm_x4(ah[i], sb + A_HI * 2 + base);
            }
            uint32_t bh[NJT][2];
#pragma unroll
            for (int jj = 0; jj < NJT / 2; jj++) {
                uint32_t base = (uint32_t)((b_off + jj * 16 * PAD + kk) * 2);
                uint32_t r[4];
                ldsm_x4(r, sb + B_HI * 2 + base);
                bh[2*jj][0] = r[0]; bh[2*jj][1] = r[1];
                bh[2*jj+1][0] = r[2]; bh[2*jj+1][1] = r[3];
            }
#pragma unroll
            for (int i = 0; i < 2; i++)
#pragma unroll
                for (int j = 0; j < NJT; j++)
                    mma_bf16(acc[i][j], ah[i], bh[j]);
        }
        __syncthreads();
    }
    #undef LOAD_CHUNK

#pragma unroll
    for (int i = 0; i < 2; i++) {
        int r0 = m0 + m_warp + i * 16 + (lane >> 2);
#pragma unroll
        for (int j = 0; j < NJT; j++) {
            int col = n_warp + j * 8 + (lane & 3) * 2;
            if (r0 < M)
                Cb[(size_t)r0 * 64 + (col >> 1)] = pack_bf16(acc[i][j][0], acc[i][j][1]);
            if (r0 + 8 < M)
                Cb[(size_t)(r0 + 8) * 64 + (col >> 1)] = pack_bf16(acc[i][j][2], acc[i][j][3]);
        }
    }
}

// =================== GEMM2: hb(bf16) @ W2hi, single-pass mma ===============
__global__ __launch_bounds__(256) void k_gemm2(
    const uint32_t* __restrict__ Ab, int M,
    const __nv_bfloat16* __restrict__ Bhi,
    uint32_t* __restrict__ Cb)
{
    constexpr int KDIM = 128, NDIM = 64, PAD2 = 136, NJT = 4;
    constexpr int A_HI = 0;
    constexpr int B_HI = 128 * PAD2;

    extern __shared__ __nv_bfloat16 sm[];
    const uint32_t sb = smem_u32(sm);

    const int tid  = threadIdx.x;
    const int wid  = tid >> 5;
    const int lane = tid & 31;
    const int wm = wid & 3;
    const int wn = wid >> 2;
    const int m_warp = wm * 32;
    const int n_warp = wn * 32;
    const int m0 = blockIdx.x * 128;

#pragma unroll
    for (int t = 0; t < 8; t++) {
        int i = tid + t * 256;
        int r = i >> 4, q = i & 15;
        int rowg = m0 + r; if (rowg >= M) rowg = M - 1;
        uint4 v = *(const uint4*)(Ab + (size_t)rowg * 64 + q * 4);
        *(uint4*)(sm + A_HI + r * PAD2 + q * 8) = v;
    }
#pragma unroll
    for (int t = 0; t < 4; t++) {
        int i = tid + t * 256;
        int r = i >> 4, q = i & 15;
        uint4 v = *(const uint4*)(Bhi + (size_t)r * KDIM + q * 8);
        *(uint4*)(sm + B_HI + r * PAD2 + q * 8) = v;
    }
    __syncthreads();

    float acc[2][NJT][4];
#pragma unroll
    for (int i = 0; i < 2; i++)
#pragma unroll
        for (int j = 0; j < NJT; j++)
#pragma unroll
            for (int q = 0; q < 4; q++) acc[i][j][q] = 0.f;

    const int a_off = (m_warp + (lane & 15)) * PAD2 + ((lane >> 4) << 3);
    const int b_off = (n_warp + (lane & 7) + ((lane >> 4) << 3)) * PAD2
                    + (((lane >> 3) & 1) << 3);

#pragma unroll
    for (int kk = 0; kk < KDIM; kk += 16) {
        uint32_t ah[2][4];
#pragma unroll
        for (int i = 0; i < 2; i++) {
            uint32_t base = (uint32_t)((a_off + i * 16 * PAD2 + kk) * 2);
            ldsm_x4(ah[i], sb + A_HI * 2 + base);
        }
        uint32_t bh[NJT][2];
#pragma unroll
        for (int jj = 0; jj < NJT / 2; jj++) {
            uint32_t base = (uint32_t)((b_off + jj * 16 * PAD2 + kk) * 2);
            uint32_t r[4];
            ldsm_x4(r, sb + B_HI * 2 + base);
            bh[2*jj][0] = r[0]; bh[2*jj][1] = r[1];
            bh[2*jj+1][0] = r[2]; bh[2*jj+1][1] = r[3];
        }
#pragma unroll
        for (int i = 0; i < 2; i++)
#pragma unroll
            for (int j = 0; j < NJT; j++)
                mma_bf16(acc[i][j], ah[i], bh[j]);
    }

#pragma unroll
    for (int i = 0; i < 2; i++) {
        int r0 = m0 + m_warp + i * 16 + (lane >> 2);
#pragma unroll
        for (int j = 0; j < NJT; j++) {
            int col = n_warp + j * 8 + (lane & 3) * 2;
            if (col < F_OUT) {
                if (r0 < M)
                    Cb[(size_t)r0 * 20 + (col >> 1)] = pack_bf16(acc[i][j][0], acc[i][j][1]);
                if (r0 + 8 < M)
                    Cb[(size_t)(r0 + 8) * 20 + (col >> 1)] = pack_bf16(acc[i][j][2], acc[i][j][3]);
            }
        }
    }
}

// bake W^T (N-major) bf16
__global__ void k_prep_b(const float* __restrict__ W, int K, int N, int nact,
                         __nv_bfloat16* __restrict__ hi) {
    int idx = blockIdx.x * blockDim.x + threadIdx.x;
    if (idx >= N * K) return;
    int n = idx / K, k = idx % K;
    float v = (n < nact) ? W[(size_t)k * nact + n] : 0.f;
    hi[idx] = __float2bfloat16(v);
}

// ---------------- preproc ---------------------------------------------------
// dtype detect + reset allocation counter (1 block)
__global__ void k_detect(const unsigned* __restrict__ w) {
    __shared__ int any;
    if (threadIdx.x == 0) { any = 0; g_total = 0; }
    __syncthreads();
    for (int j = threadIdx.x; j < 512; j += blockDim.x)
        if (w[2 * j + 1] != 0u) atomicOr(&any, 1);
    __syncthreads();
    if (threadIdx.x == 0) g_is64 = (any == 0);
}

// 2 edges per thread, vectorized reads; deg starts at 0
__global__ void k_convert(const void* __restrict__ ei) {
    int e2 = (blockIdx.x * blockDim.x + threadIdx.x) * 2;
    if (e2 >= N_EDGES) return;
    int s0, d0, s1, d1;
    if (g_is64) {
        const longlong2* ps = (const longlong2*)((const long long*)ei + e2);
        const longlong2* pd = (const longlong2*)((const long long*)ei + N_EDGES + e2);
        longlong2 sv = *ps, dv = *pd;
        s0 = (int)sv.x; s1 = (int)sv.y;
        d0 = (int)dv.x; d1 = (int)dv.y;
    } else {
        const int2* ps = (const int2*)((const int*)ei + e2);
        const int2* pd = (const int2*)((const int*)ei + N_EDGES + e2);
        int2 sv = *ps, dv = *pd;
        s0 = sv.x; s1 = sv.y;
        d0 = dv.x; d1 = dv.y;
    }
    *(int2*)(g_src + e2) = make_int2(s0, s1);
    *(int2*)(g_dst + e2) = make_int2(d0, d1);
    atomicAdd(&g_deg[d0], 1);
    atomicAdd(&g_deg[d1], 1);
}

// CSR segment allocation: block scan + one global atomic per block.
// Replaces scan1/scan2/scan3. Also emits dinv and resets deg for next replay.
__global__ __launch_bounds__(256) void k_alloc() {
    __shared__ int sh[256];
    __shared__ int sbase;
    int tid = threadIdx.x;
    int i = blockIdx.x * 256 + tid;
    int c = (i < N_NODES) ? g_deg[i] : 0;   // in-edges (self loop excluded)
    if (i < N_NODES) {
        g_dinv[i] = rsqrtf((float)(c + 1));
        g_deg[i] = 0;                        // reset for next graph replay
    }
    sh[tid] = c;
    __syncthreads();
    for (int off = 1; off < 256; off <<= 1) {
        int t = (tid >= off) ? sh[tid - off] : 0;
        __syncthreads();
        sh[tid] += t;
        __syncthreads();
    }
    if (tid == 255) sbase = atomicAdd(&g_total, sh[255]);
    __syncthreads();
    if (i < N_NODES) {
        int beg = sbase + sh[tid] - c;
        g_rowptr[i] = beg;
        g_rend[i]   = beg + c;
        g_cursor[i] = beg;
    }
}

// 2 edges per thread
__global__ void k_scatter() {
    int e2 = (blockIdx.x * blockDim.x + threadIdx.x) * 2;
    if (e2 >= N_EDGES) return;
    int2 sv = *(const int2*)(g_src + e2);
    int2 dv = *(const int2*)(g_dst + e2);
    int p0 = atomicAdd(&g_cursor[dv.x], 1);
    g_ssrc[p0] = sv.x;
    int p1 = atomicAdd(&g_cursor[dv.y], 1);
    g_ssrc[p1] = sv.y;
}

// --------- layer-1 aggregation: warp per node, bf16 in / bf16 out ---------
__device__ __forceinline__ void acc_bf16row(float4& acc, float w, uint2 u) {
    __nv_bfloat162 p0 = *reinterpret_cast<__nv_bfloat162*>(&u.x);
    __nv_bfloat162 p1 = *reinterpret_cast<__nv_bfloat162*>(&u.y);
    acc.x += w * __low2float(p0);
    acc.y += w * __high2float(p0);
    acc.z += w * __low2float(p1);
    acc.w += w * __high2float(p1);
}

__global__ __launch_bounds__(256) void k_agg1(const float* __restrict__ b1) {
    int node = (blockIdx.x * blockDim.x + threadIdx.x) >> 5;
    if (node >= N_NODES) return;
    int lane = threadIdx.x & 31;
    float di = g_dinv[node];
    float wself = di * di;

    float4 acc = make_float4(0.f, 0.f, 0.f, 0.f);
    acc_bf16row(acc, wself, ((const uint2*)(g_H1b + (size_t)node * 64))[lane]);

    int beg = g_rowptr[node], end = g_rend[node];
    for (int p0 = beg; p0 < end; p0 += 32) {
        int myp = p0 + lane;
        int s = (myp < end) ? g_ssrc[myp] : 0;
        float ws = (myp < end) ? g_dinv[s] * di : 0.f;
        int cnt = min(32, end - p0);
        int j = 0;
        for (; j + 4 <= cnt; j += 4) {
            int   s0 = __shfl_sync(0xffffffffu, s, j);
            int   s1 = __shfl_sync(0xffffffffu, s, j + 1);
            int   s2 = __shfl_sync(0xffffffffu, s, j + 2);
            int   s3 = __shfl_sync(0xffffffffu, s, j + 3);
            float w0 = __shfl_sync(0xffffffffu, ws, j);
            float w1 = __shfl_sync(0xffffffffu, ws, j + 1);
            float w2 = __shfl_sync(0xffffffffu, ws, j + 2);
            float w3 = __shfl_sync(0xffffffffu, ws, j + 3);
            uint2 u0 = ((const uint2*)(g_H1b + (size_t)s0 * 64))[lane];
            uint2 u1 = ((const uint2*)(g_H1b + (size_t)s1 * 64))[lane];
            uint2 u2 = ((const uint2*)(g_H1b + (size_t)s2 * 64))[lane];
            uint2 u3 = ((const uint2*)(g_H1b + (size_t)s3 * 64))[lane];
            acc_bf16row(acc, w0, u0);
            acc_bf16row(acc, w1, u1);
            acc_bf16row(acc, w2, u2);
            acc_bf16row(acc, w3, u3);
        }
        for (; j < cnt; ++j) {
            int   sj = __shfl_sync(0xffffffffu, s, j);
            float wj = __shfl_sync(0xffffffffu, ws, j);
            acc_bf16row(acc, wj, ((const uint2*)(g_H1b + (size_t)sj * 64))[lane]);
        }
    }
    float4 bb = ((const float4*)b1)[lane];
    acc.x = fmaxf(acc.x + bb.x, 0.f);
    acc.y = fmaxf(acc.y + bb.y, 0.f);
    acc.z = fmaxf(acc.z + bb.z, 0.f);
    acc.w = fmaxf(acc.w + bb.w, 0.f);
    uint2 packed = make_uint2(pack_bf16(acc.x, acc.y), pack_bf16(acc.z, acc.w));
    ((uint2*)(g_hb + (size_t)node * 64))[lane] = packed;
}

// ---- layer-2 aggregation (bf16 H2 gather) + bias + log_softmax ------------
__global__ __launch_bounds__(256) void k_agg2(const float* __restrict__ b2,
                                              float* __restrict__ out) {
    int node = (blockIdx.x * blockDim.x + threadIdx.x) >> 5;
    if (node >= N_NODES) return;
    int lane = threadIdx.x & 31;
    bool act = lane < 20;                  // 20 u32 = 40 cols
    float di = g_dinv[node];
    float wself = di * di;

    int llane = act ? lane : 0;
    float acc0 = 0.f, acc1 = 0.f;
    {
        uint32_t u = g_H2b[(size_t)node * 20 + llane];
        __nv_bfloat162 p = *reinterpret_cast<__nv_bfloat162*>(&u);
        acc0 = wself * __low2float(p);
        acc1 = wself * __high2float(p);
    }

    int beg = g_rowptr[node], end = g_rend[node];
    for (int p0 = beg; p0 < end; p0 += 32) {
        int myp = p0 + lane;
        int s = (myp < end) ? g_ssrc[myp] : 0;
        float ws = (myp < end) ? g_dinv[s] * di : 0.f;
        int cnt = min(32, end - p0);
        int j = 0;
        for (; j + 4 <= cnt; j += 4) {
            int   s0 = __shfl_sync(0xffffffffu, s, j);
            int   s1 = __shfl_sync(0xffffffffu, s, j + 1);
            int   s2 = __shfl_sync(0xffffffffu, s, j + 2);
            int   s3 = __shfl_sync(0xffffffffu, s, j + 3);
            float w0 = __shfl_sync(0xffffffffu, ws, j);
            float w1 = __shfl_sync(0xffffffffu, ws, j + 1);
            float w2 = __shfl_sync(0xffffffffu, ws, j + 2);
            float w3 = __shfl_sync(0xffffffffu, ws, j + 3);
            uint32_t u0 = g_H2b[(size_t)s0 * 20 + llane];
            uint32_t u1 = g_H2b[(size_t)s1 * 20 + llane];
            uint32_t u2 = g_H2b[(size_t)s2 * 20 + llane];
            uint32_t u3 = g_H2b[(size_t)s3 * 20 + llane];
            __nv_bfloat162 q0 = *reinterpret_cast<__nv_bfloat162*>(&u0);
            __nv_bfloat162 q1 = *reinterpret_cast<__nv_bfloat162*>(&u1);
            __nv_bfloat162 q2 = *reinterpret_cast<__nv_bfloat162*>(&u2);
            __nv_bfloat162 q3 = *reinterpret_cast<__nv_bfloat162*>(&u3);
            acc0 += w0 * __low2float(q0) + w1 * __low2float(q1)
                  + w2 * __low2float(q2) + w3 * __low2float(q3);
            acc1 += w0 * __high2float(q0) + w1 * __high2float(q1)
                  + w2 * __high2float(q2) + w3 * __high2float(q3);
        }
        for (; j < cnt; ++j) {
            int   sj = __shfl_sync(0xffffffffu, s, j);
            float wj = __shfl_sync(0xffffffffu, ws, j);
            uint32_t u = g_H2b[(size_t)sj * 20 + llane];
            __nv_bfloat162 q = *reinterpret_cast<__nv_bfloat162*>(&u);
            acc0 += wj * __low2float(q);
            acc1 += wj * __high2float(q);
        }
    }
    acc0 += b2[2 * llane];
    acc1 += b2[2 * llane + 1];

    float m = act ? fmaxf(acc0, acc1) : -1e30f;
#pragma unroll
    for (int o = 16; o; o >>= 1) m = fmaxf(m, __shfl_xor_sync(0xffffffffu, m, o));
    float e = act ? (expf(acc0 - m) + expf(acc1 - m)) : 0.f;
#pragma unroll
    for (int o = 16; o; o >>= 1) e += __shfl_xor_sync(0xffffffffu, e, o);
    float lse = m + logf(e);

    if (act) {
        float2 o2 = make_float2(acc0 - lse, acc1 - lse);
        *(float2*)(out + (size_t)node * F_OUT + 2 * lane) = o2;
    }
}

// ---------------- host launcher --------------------------------------------
extern "C" void kernel_launch(void* const* d_in, const int* in_sizes, int n_in,
                              void* d_out, int out_size) {
    const float* x  = (const float*)d_in[0];
    const void*  ei = d_in[1];
    const float* W1 = (const float*)d_in[2];
    const float* b1 = (const float*)d_in[3];
    const float* W2 = (const float*)d_in[4];
    const float* b2 = (const float*)d_in[5];
    float* out = (float*)d_out;

    uint32_t *dH1b, *dhb, *dH2b;
    __nv_bfloat16 *dB1hi, *dB2hi;
    cudaGetSymbolAddress((void**)&dH1b,  g_H1b);
    cudaGetSymbolAddress((void**)&dhb,   g_hb);
    cudaGetSymbolAddress((void**)&dH2b,  g_H2b);
    cudaGetSymbolAddress((void**)&dB1hi, g_B1hi);
    cudaGetSymbolAddress((void**)&dB2hi, g_B2hi);

    const int SMEM1 = (128 + 128) * 72 * 2;       // 36864
    const int SMEM2 = (128 + 64) * 136 * 2;       // 52224

    static cudaStream_t s2;
    static cudaEvent_t evFork, evJoin;
    static bool init_done = false;
    if (!init_done) {
        cudaFuncSetAttribute(k_gemm1,
                             cudaFuncAttributeMaxDynamicSharedMemorySize, SMEM1);
        cudaFuncSetAttribute(k_gemm2,
                             cudaFuncAttributeMaxDynamicSharedMemorySize, SMEM2);
        cudaStreamCreateWithFlags(&s2, cudaStreamNonBlocking);
        cudaEventCreateWithFlags(&evFork, cudaEventDisableTiming);
        cudaEventCreateWithFlags(&evJoin, cudaEventDisableTiming);
        init_done = true;
    }

    const int TB = 256;
    int nblkN = (N_NODES + TB - 1) / TB;          // 391
    int nblkE2 = (N_EDGES / 2 + TB - 1) / TB;     // 3125 (2 edges/thread)
    int aggBlk = (N_NODES * 32) / TB;
    int gemmBlk = (N_NODES + 127) / 128;          // 782

    // ---- fork: side stream = weights + GEMM1; main stream = CSR build ----
    cudaEventRecord(evFork, 0);
    cudaStreamWaitEvent(s2, evFork, 0);

    k_prep_b<<<(128 * 256 + TB - 1) / TB, TB, 0, s2>>>(W1, 256, 128, 128, dB1hi);
    k_prep_b<<<(64 * 128 + TB - 1) / TB, TB, 0, s2>>>(W2, 128, 64, 40, dB2hi);
    k_gemm1<<<gemmBlk, 256, SMEM1, s2>>>(x, N_NODES, dB1hi, dH1b);

    k_detect<<<1, 256>>>((const unsigned*)ei);
    k_convert<<<nblkE2, TB>>>(ei);
    k_alloc<<<nblkN, TB>>>();
    k_scatter<<<nblkE2, TB>>>();

    cudaEventRecord(evJoin, s2);
    cudaStreamWaitEvent(0, evJoin, 0);

    // agg1 (bf16 in/out), GEMM2 (1-pass), agg2 (bf16 gather) + log_softmax
    k_agg1<<<aggBlk, TB>>>(b1);
    k_gemm2<<<gemmBlk, 256, SMEM2>>>(dhb, N_NODES, dB2hi, dH2b);
    k_agg2<<<aggBlk, TB>>>(b2, out);
}

// round 12
// speedup vs baseline: 1.5370x; 1.0176x over previous
#include <cuda_runtime.h>
#include <cuda_bf16.h>
#include <math.h>
#include <stdint.h>

#define N_NODES 100000
#define N_EDGES 1600000
#define F_IN    256
#define F_HID   128
#define F_OUT   40

// ---------------- device scratch (static globals: allowed) ----------------
__device__ int   g_total;               // CSR allocation counter (reset in k_deg)
__device__ int   g_deg[N_NODES];        // zero-init; self-resets in k_alloc
__device__ float g_dinv[N_NODES];
__device__ int   g_rowptr[N_NODES];
__device__ int   g_rend[N_NODES];
__device__ int   g_cursor[N_NODES];
__device__ int   g_ssrc[N_EDGES];       // src ids grouped by dst segment
__device__ uint32_t g_H1b[(size_t)N_NODES * 64];   // x @ W1, packed bf16x2
__device__ uint32_t g_hb [(size_t)N_NODES * 64];   // relu(agg1+b1), packed bf16x2
__device__ uint32_t g_H2b[(size_t)N_NODES * 20];   // h @ W2, packed bf16x2
// W^T baked as N-major bf16: [N][K]
__device__ __align__(16) __nv_bfloat16 g_B1hi[128 * 256];
__device__ __align__(16) __nv_bfloat16 g_B2hi[64 * 128];

// ======================= mma.sync helpers ==================================
__device__ __forceinline__ uint32_t smem_u32(const void* p) {
    uint32_t a;
    asm("{ .reg .u64 t; cvta.to.shared.u64 t, %1; cvt.u32.u64 %0, t; }"
        : "=r"(a) : "l"(p));
    return a;
}

__device__ __forceinline__ void ldsm_x4(uint32_t* r, uint32_t addr) {
    asm volatile("ldmatrix.sync.aligned.m8n8.x4.shared.b16 {%0,%1,%2,%3}, [%4];"
                 : "=r"(r[0]), "=r"(r[1]), "=r"(r[2]), "=r"(r[3]) : "r"(addr));
}

__device__ __forceinline__ void mma_bf16(float* c, const uint32_t* a, const uint32_t* b) {
    asm volatile(
        "mma.sync.aligned.m16n8k16.row.col.f32.bf16.bf16.f32 "
        "{%0,%1,%2,%3}, {%4,%5,%6,%7}, {%8,%9}, {%0,%1,%2,%3};"
        : "+f"(c[0]), "+f"(c[1]), "+f"(c[2]), "+f"(c[3])
        : "r"(a[0]), "r"(a[1]), "r"(a[2]), "r"(a[3]), "r"(b[0]), "r"(b[1]));
}

__device__ __forceinline__ uint32_t pack_bf16(float a, float b) {
    __nv_bfloat16 x = __float2bfloat16(a), y = __float2bfloat16(b);
    return ((uint32_t)__bfloat16_as_ushort(y) << 16) | __bfloat16_as_ushort(x);
}

// per-block dtype detection: int64 edge_index (values < 2^31) has all odd
// 32-bit words zero in the first 4KB; int32 random ids make that impossible.
__device__ __forceinline__ int detect_is64_block(const unsigned* w) {
    __shared__ int any;
    if (threadIdx.x == 0) any = 0;
    __syncthreads();
    int loc = 0;
    for (int j = threadIdx.x; j < 512; j += blockDim.x)
        if (w[2 * j + 1] != 0u) loc = 1;
    if (__syncthreads_or(loc)) return 0;
    return 1;
}

// =================== GEMM1: x @ W1, single-pass bf16 =======================
__global__ __launch_bounds__(256) void k_gemm1(
    const float* __restrict__ A, int M,
    const __nv_bfloat16* __restrict__ Bhi,
    uint32_t* __restrict__ Cb)
{
    constexpr int KDIM = 256, NDIM = 128, PAD = 72, NJT = 8;
    constexpr int A_HI = 0;
    constexpr int B_HI = 128 * PAD;

    extern __shared__ __nv_bfloat16 sm[];
    const uint32_t sb = smem_u32(sm);

    const int tid  = threadIdx.x;
    const int wid  = tid >> 5;
    const int lane = tid & 31;
    const int wm = wid & 3;
    const int wn = wid >> 2;
    const int m_warp = wm * 32;
    const int n_warp = wn * 64;
    const int m0 = blockIdx.x * 128;

    float acc[2][NJT][4];
#pragma unroll
    for (int i = 0; i < 2; i++)
#pragma unroll
        for (int j = 0; j < NJT; j++)
#pragma unroll
            for (int q = 0; q < 4; q++) acc[i][j][q] = 0.f;

    const int a_off = (m_warp + (lane & 15)) * PAD + ((lane >> 4) << 3);
    const int b_off = (n_warp + (lane & 7) + ((lane >> 4) << 3)) * PAD
                    + (((lane >> 3) & 1) << 3);

    float4 areg[8];
    uint4  breg[4];
    #define LOAD_CHUNK(k0) do {                                               \
        _Pragma("unroll")                                                     \
        for (int t = 0; t < 8; t++) {                                         \
            int i = tid + t * 256;                                            \
            int m = i >> 4, q = i & 15;                                       \
            int rowg = m0 + m; if (rowg >= M) rowg = M - 1;                   \
            areg[t] = *(const float4*)(A + (size_t)rowg * KDIM + (k0) + q * 4); \
        }                                                                     \
        _Pragma("unroll")                                                     \
        for (int t = 0; t < 4; t++) {                                         \
            int i = tid + t * 256;                                            \
            int r = i >> 3, q = i & 7;                                        \
            breg[t] = *(const uint4*)(Bhi + (size_t)r * KDIM + (k0) + q * 8); \
        }                                                                     \
    } while (0)

    LOAD_CHUNK(0);

    for (int k0 = 0; k0 < KDIM; k0 += 64) {
#pragma unroll
        for (int t = 0; t < 8; t++) {
            int i = tid + t * 256;
            int m = i >> 4, q = i & 15;
            float4 v = areg[t];
            *(uint2*)(sm + A_HI + m * PAD + q * 4) =
                make_uint2(pack_bf16(v.x, v.y), pack_bf16(v.z, v.w));
        }
#pragma unroll
        for (int t = 0; t < 4; t++) {
            int i = tid + t * 256;
            int r = i >> 3, q = i & 7;
            *(uint4*)(sm + B_HI + r * PAD + q * 8) = breg[t];
        }
        __syncthreads();

        if (k0 + 64 < KDIM) LOAD_CHUNK(k0 + 64);

#pragma unroll
        for (int kk = 0; kk < 64; kk += 16) {
            uint32_t ah[2][4];
#pragma unroll
            for (int i = 0; i < 2; i++) {
                uint32_t base = (uint32_t)((a_off + i * 16 * PAD + kk) * 2);
                ldsm_x4(ah[i], sb + A_HI * 2 + base);
            }
            uint32_t bh[NJT][2];
#pragma unroll
            for (int jj = 0; jj < NJT / 2; jj++) {
                uint32_t base = (uint32_t)((b_off + jj * 16 * PAD + kk) * 2);
                uint32_t r[4];
                ldsm_x4(r, sb + B_HI * 2 + base);
                bh[2*jj][0] = r[0]; bh[2*jj][1] = r[1];
                bh[2*jj+1][0] = r[2]; bh[2*jj+1][1] = r[3];
            }
#pragma unroll
            for (int i = 0; i < 2; i++)
#pragma unroll
                for (int j = 0; j < NJT; j++)
                    mma_bf16(acc[i][j], ah[i], bh[j]);
        }
        __syncthreads();
    }
    #undef LOAD_CHUNK

#pragma unroll
    for (int i = 0; i < 2; i++) {
        int r0 = m0 + m_warp + i * 16 + (lane >> 2);
#pragma unroll
        for (int j = 0; j < NJT; j++) {
            int col = n_warp + j * 8 + (lane & 3) * 2;
            if (r0 < M)
                Cb[(size_t)r0 * 64 + (col >> 1)] = pack_bf16(acc[i][j][0], acc[i][j][1]);
            if (r0 + 8 < M)
                Cb[(size_t)(r0 + 8) * 64 + (col >> 1)] = pack_bf16(acc[i][j][2], acc[i][j][3]);
        }
    }
}

// =================== GEMM2: hb(bf16) @ W2hi, single-pass mma ===============
__global__ __launch_bounds__(256) void k_gemm2(
    const uint32_t* __restrict__ Ab, int M,
    const __nv_bfloat16* __restrict__ Bhi,
    uint32_t* __restrict__ Cb)
{
    constexpr int KDIM = 128, NDIM = 64, PAD2 = 136, NJT = 4;
    constexpr int A_HI = 0;
    constexpr int B_HI = 128 * PAD2;

    extern __shared__ __nv_bfloat16 sm[];
    const uint32_t sb = smem_u32(sm);

    const int tid  = threadIdx.x;
    const int wid  = tid >> 5;
    const int lane = tid & 31;
    const int wm = wid & 3;
    const int wn = wid >> 2;
    const int m_warp = wm * 32;
    const int n_warp = wn * 32;
    const int m0 = blockIdx.x * 128;

#pragma unroll
    for (int t = 0; t < 8; t++) {
        int i = tid + t * 256;
        int r = i >> 4, q = i & 15;
        int rowg = m0 + r; if (rowg >= M) rowg = M - 1;
        uint4 v = *(const uint4*)(Ab + (size_t)rowg * 64 + q * 4);
        *(uint4*)(sm + A_HI + r * PAD2 + q * 8) = v;
    }
#pragma unroll
    for (int t = 0; t < 4; t++) {
        int i = tid + t * 256;
        int r = i >> 4, q = i & 15;
        uint4 v = *(const uint4*)(Bhi + (size_t)r * KDIM + q * 8);
        *(uint4*)(sm + B_HI + r * PAD2 + q * 8) = v;
    }
    __syncthreads();

    float acc[2][NJT][4];
#pragma unroll
    for (int i = 0; i < 2; i++)
#pragma unroll
        for (int j = 0; j < NJT; j++)
#pragma unroll
            for (int q = 0; q < 4; q++) acc[i][j][q] = 0.f;

    const int a_off = (m_warp + (lane & 15)) * PAD2 + ((lane >> 4) << 3);
    const int b_off = (n_warp + (lane & 7) + ((lane >> 4) << 3)) * PAD2
                    + (((lane >> 3) & 1) << 3);

#pragma unroll
    for (int kk = 0; kk < KDIM; kk += 16) {
        uint32_t ah[2][4];
#pragma unroll
        for (int i = 0; i < 2; i++) {
            uint32_t base = (uint32_t)((a_off + i * 16 * PAD2 + kk) * 2);
            ldsm_x4(ah[i], sb + A_HI * 2 + base);
        }
        uint32_t bh[NJT][2];
#pragma unroll
        for (int jj = 0; jj < NJT / 2; jj++) {
            uint32_t base = (uint32_t)((b_off + jj * 16 * PAD2 + kk) * 2);
            uint32_t r[4];
            ldsm_x4(r, sb + B_HI * 2 + base);
            bh[2*jj][0] = r[0]; bh[2*jj][1] = r[1];
            bh[2*jj+1][0] = r[2]; bh[2*jj+1][1] = r[3];
        }
#pragma unroll
        for (int i = 0; i < 2; i++)
#pragma unroll
            for (int j = 0; j < NJT; j++)
                mma_bf16(acc[i][j], ah[i], bh[j]);
    }

#pragma unroll
    for (int i = 0; i < 2; i++) {
        int r0 = m0 + m_warp + i * 16 + (lane >> 2);
#pragma unroll
        for (int j = 0; j < NJT; j++) {
            int col = n_warp + j * 8 + (lane & 3) * 2;
            if (col < F_OUT) {
                if (r0 < M)
                    Cb[(size_t)r0 * 20 + (col >> 1)] = pack_bf16(acc[i][j][0], acc[i][j][1]);
                if (r0 + 8 < M)
                    Cb[(size_t)(r0 + 8) * 20 + (col >> 1)] = pack_bf16(acc[i][j][2], acc[i][j][3]);
            }
        }
    }
}

// bake W^T (N-major) bf16
__global__ void k_prep_b(const float* __restrict__ W, int K, int N, int nact,
                         __nv_bfloat16* __restrict__ hi) {
    int idx = blockIdx.x * blockDim.x + threadIdx.x;
    if (idx >= N * K) return;
    int n = idx / K, k = idx % K;
    float v = (n < nact) ? W[(size_t)k * nact + n] : 0.f;
    hi[idx] = __float2bfloat16(v);
}

// ---------------- preproc ---------------------------------------------------
// degree histogram (reads dst half only, dtype detected per block)
__global__ void k_deg(const void* __restrict__ ei) {
    int is64 = detect_is64_block((const unsigned*)ei);
    if (blockIdx.x == 0 && threadIdx.x == 0) g_total = 0;
    int e2 = (blockIdx.x * blockDim.x + threadIdx.x) * 2;
    if (e2 >= N_EDGES) return;
    int d0, d1;
    if (is64) {
        longlong2 dv = *(const longlong2*)((const long long*)ei + N_EDGES + e2);
        d0 = (int)dv.x; d1 = (int)dv.y;
    } else {
        int2 dv = *(const int2*)((const int*)ei + N_EDGES + e2);
        d0 = dv.x; d1 = dv.y;
    }
    atomicAdd(&g_deg[d0], 1);
    atomicAdd(&g_deg[d1], 1);
}

// CSR segment allocation: block scan + one global atomic per block.
// Emits rowptr/rend/cursor/dinv, resets deg for next replay.
__global__ __launch_bounds__(256) void k_alloc() {
    __shared__ int sh[256];
    __shared__ int sbase;
    int tid = threadIdx.x;
    int i = blockIdx.x * 256 + tid;
    int c = (i < N_NODES) ? g_deg[i] : 0;
    if (i < N_NODES) {
        g_dinv[i] = rsqrtf((float)(c + 1));
        g_deg[i] = 0;
    }
    sh[tid] = c;
    __syncthreads();
    for (int off = 1; off < 256; off <<= 1) {
        int t = (tid >= off) ? sh[tid - off] : 0;
        __syncthreads();
        sh[tid] += t;
        __syncthreads();
    }
    if (tid == 255) sbase = atomicAdd(&g_total, sh[255]);
    __syncthreads();
    if (i < N_NODES) {
        int beg = sbase + sh[tid] - c;
        g_rowptr[i] = beg;
        g_rend[i]   = beg + c;
        g_cursor[i] = beg;
    }
}

// scatter: re-parses edge_index directly (no staging arrays)
__global__ void k_scatter(const void* __restrict__ ei) {
    int is64 = detect_is64_block((const unsigned*)ei);
    int e2 = (blockIdx.x * blockDim.x + threadIdx.x) * 2;
    if (e2 >= N_EDGES) return;
    int s0, s1, d0, d1;
    if (is64) {
        longlong2 sv = *(const longlong2*)((const long long*)ei + e2);
        longlong2 dv = *(const longlong2*)((const long long*)ei + N_EDGES + e2);
        s0 = (int)sv.x; s1 = (int)sv.y;
        d0 = (int)dv.x; d1 = (int)dv.y;
    } else {
        int2 sv = *(const int2*)((const int*)ei + e2);
        int2 dv = *(const int2*)((const int*)ei + N_EDGES + e2);
        s0 = sv.x; s1 = sv.y;
        d0 = dv.x; d1 = dv.y;
    }
    int p0 = atomicAdd(&g_cursor[d0], 1);
    g_ssrc[p0] = s0;
    int p1 = atomicAdd(&g_cursor[d1], 1);
    g_ssrc[p1] = s1;
}

// --------- layer-1 aggregation: warp per node, bf16 in / bf16 out ---------
__device__ __forceinline__ void acc_bf16row(float4& acc, float w, uint2 u) {
    __nv_bfloat162 p0 = *reinterpret_cast<__nv_bfloat162*>(&u.x);
    __nv_bfloat162 p1 = *reinterpret_cast<__nv_bfloat162*>(&u.y);
    acc.x += w * __low2float(p0);
    acc.y += w * __high2float(p0);
    acc.z += w * __low2float(p1);
    acc.w += w * __high2float(p1);
}

__global__ __launch_bounds__(256) void k_agg1(const float* __restrict__ b1) {
    int node = (blockIdx.x * blockDim.x + threadIdx.x) >> 5;
    if (node >= N_NODES) return;
    int lane = threadIdx.x & 31;
    float di = g_dinv[node];
    float wself = di * di;

    float4 acc = make_float4(0.f, 0.f, 0.f, 0.f);
    acc_bf16row(acc, wself, ((const uint2*)(g_H1b + (size_t)node * 64))[lane]);

    int beg = g_rowptr[node], end = g_rend[node];
    for (int p0 = beg; p0 < end; p0 += 32) {
        int myp = p0 + lane;
        int s = (myp < end) ? g_ssrc[myp] : 0;
        float ws = (myp < end) ? g_dinv[s] * di : 0.f;
        int cnt = min(32, end - p0);
        int j = 0;
        for (; j + 4 <= cnt; j += 4) {
            int   s0 = __shfl_sync(0xffffffffu, s, j);
            int   s1 = __shfl_sync(0xffffffffu, s, j + 1);
            int   s2 = __shfl_sync(0xffffffffu, s, j + 2);
            int   s3 = __shfl_sync(0xffffffffu, s, j + 3);
            float w0 = __shfl_sync(0xffffffffu, ws, j);
            float w1 = __shfl_sync(0xffffffffu, ws, j + 1);
            float w2 = __shfl_sync(0xffffffffu, ws, j + 2);
            float w3 = __shfl_sync(0xffffffffu, ws, j + 3);
            uint2 u0 = ((const uint2*)(g_H1b + (size_t)s0 * 64))[lane];
            uint2 u1 = ((const uint2*)(g_H1b + (size_t)s1 * 64))[lane];
            uint2 u2 = ((const uint2*)(g_H1b + (size_t)s2 * 64))[lane];
            uint2 u3 = ((const uint2*)(g_H1b + (size_t)s3 * 64))[lane];
            acc_bf16row(acc, w0, u0);
            acc_bf16row(acc, w1, u1);
            acc_bf16row(acc, w2, u2);
            acc_bf16row(acc, w3, u3);
        }
        for (; j < cnt; ++j) {
            int   sj = __shfl_sync(0xffffffffu, s, j);
            float wj = __shfl_sync(0xffffffffu, ws, j);
            acc_bf16row(acc, wj, ((const uint2*)(g_H1b + (size_t)sj * 64))[lane]);
        }
    }
    float4 bb = ((const float4*)b1)[lane];
    acc.x = fmaxf(acc.x + bb.x, 0.f);
    acc.y = fmaxf(acc.y + bb.y, 0.f);
    acc.z = fmaxf(acc.z + bb.z, 0.f);
    acc.w = fmaxf(acc.w + bb.w, 0.f);
    uint2 packed = make_uint2(pack_bf16(acc.x, acc.y), pack_bf16(acc.z, acc.w));
    ((uint2*)(g_hb + (size_t)node * 64))[lane] = packed;
}

// ---- layer-2 aggregation (bf16 H2 gather) + bias + log_softmax ------------
__global__ __launch_bounds__(256) void k_agg2(const float* __restrict__ b2,
                                              float* __restrict__ out) {
    int node = (blockIdx.x * blockDim.x + threadIdx.x) >> 5;
    if (node >= N_NODES) return;
    int lane = threadIdx.x & 31;
    bool act = lane < 20;
    float di = g_dinv[node];
    float wself = di * di;

    int llane = act ? lane : 0;
    float acc0 = 0.f, acc1 = 0.f;
    {
        uint32_t u = g_H2b[(size_t)node * 20 + llane];
        __nv_bfloat162 p = *reinterpret_cast<__nv_bfloat162*>(&u);
        acc0 = wself * __low2float(p);
        acc1 = wself * __high2float(p);
    }

    int beg = g_rowptr[node], end = g_rend[node];
    for (int p0 = beg; p0 < end; p0 += 32) {
        int myp = p0 + lane;
        int s = (myp < end) ? g_ssrc[myp] : 0;
        float ws = (myp < end) ? g_dinv[s] * di : 0.f;
        int cnt = min(32, end - p0);
        int j = 0;
        for (; j + 4 <= cnt; j += 4) {
            int   s0 = __shfl_sync(0xffffffffu, s, j);
            int   s1 = __shfl_sync(0xffffffffu, s, j + 1);
            int   s2 = __shfl_sync(0xffffffffu, s, j + 2);
            int   s3 = __shfl_sync(0xffffffffu, s, j + 3);
            float w0 = __shfl_sync(0xffffffffu, ws, j);
            float w1 = __shfl_sync(0xffffffffu, ws, j + 1);
            float w2 = __shfl_sync(0xffffffffu, ws, j + 2);
            float w3 = __shfl_sync(0xffffffffu, ws, j + 3);
            uint32_t u0 = g_H2b[(size_t)s0 * 20 + llane];
            uint32_t u1 = g_H2b[(size_t)s1 * 20 + llane];
            uint32_t u2 = g_H2b[(size_t)s2 * 20 + llane];
            uint32_t u3 = g_H2b[(size_t)s3 * 20 + llane];
            __nv_bfloat162 q0 = *reinterpret_cast<__nv_bfloat162*>(&u0);
            __nv_bfloat162 q1 = *reinterpret_cast<__nv_bfloat162*>(&u1);
            __nv_bfloat162 q2 = *reinterpret_cast<__nv_bfloat162*>(&u2);
            __nv_bfloat162 q3 = *reinterpret_cast<__nv_bfloat162*>(&u3);
            acc0 += w0 * __low2float(q0) + w1 * __low2float(q1)
                  + w2 * __low2float(q2) + w3 * __low2float(q3);
            acc1 += w0 * __high2float(q0) + w1 * __high2float(q1)
                  + w2 * __high2float(q2) + w3 * __high2float(q3);
        }
        for (; j < cnt; ++j) {
            int   sj = __shfl_sync(0xffffffffu, s, j);
            float wj = __shfl_sync(0xffffffffu, ws, j);
            uint32_t u = g_H2b[(size_t)sj * 20 + llane];
            __nv_bfloat162 q = *reinterpret_cast<__nv_bfloat162*>(&u);
            acc0 += wj * __low2float(q);
            acc1 += wj * __high2float(q);
        }
    }
    acc0 += b2[2 * llane];
    acc1 += b2[2 * llane + 1];

    float m = act ? fmaxf(acc0, acc1) : -1e30f;
#pragma unroll
    for (int o = 16; o; o >>= 1) m = fmaxf(m, __shfl_xor_sync(0xffffffffu, m, o));
    float e = act ? (expf(acc0 - m) + expf(acc1 - m)) : 0.f;
#pragma unroll
    for (int o = 16; o; o >>= 1) e += __shfl_xor_sync(0xffffffffu, e, o);
    float lse = m + logf(e);

    if (act) {
        float2 o2 = make_float2(acc0 - lse, acc1 - lse);
        *(float2*)(out + (size_t)node * F_OUT + 2 * lane) = o2;
    }
}

// ---------------- host launcher --------------------------------------------
extern "C" void kernel_launch(void* const* d_in, const int* in_sizes, int n_in,
                              void* d_out, int out_size) {
    const float* x  = (const float*)d_in[0];
    const void*  ei = d_in[1];
    const float* W1 = (const float*)d_in[2];
    const float* b1 = (const float*)d_in[3];
    const float* W2 = (const float*)d_in[4];
    const float* b2 = (const float*)d_in[5];
    float* out = (float*)d_out;

    uint32_t *dH1b, *dhb, *dH2b;
    __nv_bfloat16 *dB1hi, *dB2hi;
    cudaGetSymbolAddress((void**)&dH1b,  g_H1b);
    cudaGetSymbolAddress((void**)&dhb,   g_hb);
    cudaGetSymbolAddress((void**)&dH2b,  g_H2b);
    cudaGetSymbolAddress((void**)&dB1hi, g_B1hi);
    cudaGetSymbolAddress((void**)&dB2hi, g_B2hi);

    const int SMEM1 = (128 + 128) * 72 * 2;       // 36864
    const int SMEM2 = (128 + 64) * 136 * 2;       // 52224

    static cudaStream_t s2;
    static cudaEvent_t evFork, evJoin, evJoin2;
    static bool init_done = false;
    if (!init_done) {
        cudaFuncSetAttribute(k_gemm1,
                             cudaFuncAttributeMaxDynamicSharedMemorySize, SMEM1);
        cudaFuncSetAttribute(k_gemm2,
                             cudaFuncAttributeMaxDynamicSharedMemorySize, SMEM2);
        cudaStreamCreateWithFlags(&s2, cudaStreamNonBlocking);
        cudaEventCreateWithFlags(&evFork, cudaEventDisableTiming);
        cudaEventCreateWithFlags(&evJoin, cudaEventDisableTiming);
        cudaEventCreateWithFlags(&evJoin2, cudaEventDisableTiming);
        init_done = true;
    }

    const int TB = 256;
    int nblkN = (N_NODES + TB - 1) / TB;          // 391
    int nblkE2 = (N_EDGES / 2 + TB - 1) / TB;     // 3125 (2 edges/thread)
    int aggBlk = (N_NODES * 32) / TB;
    int gemmBlk = (N_NODES + 127) / 128;          // 782

    // ---- fork: side stream = W1 bake + GEMM1 (+ W2 bake late);
    //      main stream = CSR build ----
    cudaEventRecord(evFork, 0);
    cudaStreamWaitEvent(s2, evFork, 0);

    k_prep_b<<<(128 * 256 + TB - 1) / TB, TB, 0, s2>>>(W1, 256, 128, 128, dB1hi);
    k_gemm1<<<gemmBlk, 256, SMEM1, s2>>>(x, N_NODES, dB1hi, dH1b);
    cudaEventRecord(evJoin, s2);
    // W2 bake off the critical path (only gemm2 needs it; hides under agg1)
    k_prep_b<<<(64 * 128 + TB - 1) / TB, TB, 0, s2>>>(W2, 128, 64, 40, dB2hi);
    cudaEventRecord(evJoin2, s2);

    k_deg<<<nblkE2, TB>>>(ei);
    k_alloc<<<nblkN, TB>>>();
    k_scatter<<<nblkE2, TB>>>(ei);

    cudaStreamWaitEvent(0, evJoin, 0);

    // agg1 (bf16 in/out), GEMM2 (1-pass), agg2 (bf16 gather) + log_softmax
    k_agg1<<<aggBlk, TB>>>(b1);
    cudaStreamWaitEvent(0, evJoin2, 0);
    k_gemm2<<<gemmBlk, 256, SMEM2>>>(dhb, N_NODES, dB2hi, dH2b);
    k_agg2<<<aggBlk, TB>>>(b2, out);
}